// round 11
// baseline (speedup 1.0000x reference)
#include <cuda_runtime.h>
#include <cuda_bf16.h>
#include <math.h>
#include <stdint.h>

#define BATCH   16
#define CIN     256
#define HH      56
#define WW      56
#define HEADS   4
#define CPER    64
#define HB_N    64
#define NPIX    3136
#define NOUT    (BATCH*HEADS*CPER*NPIX)
#define BN_EPS  1e-5f

#define PGRID   58
#define PTOT    (PGRID*PGRID)    // 3364
#define NTILES  26
#define PLROWS  246
#define GROW    3520             // padded plane rows in gmem (64 guard + 3364 + tail)

// smem layout (bytes)
#define WTILE_B  18432           // 144 rows * 128 B (swizzled)
#define OFF_W0H  0
#define OFF_W0L  18432
#define OFF_W1H  36864
#define OFF_W1L  55296
#define OFF_P0   73728           // plane buf0: 246 rows * 80 B = 19680
#define OFF_P1   93408
#define OFF_C    113088          // sch[2][16]
#define SMEM_BYTES 113216

__device__ float g_xavg[BATCH*CIN];
__device__ int   g_act_idx[HB_N*256];
__device__ float g_act_val[HB_N*256];
__device__ int   g_act_cnt[HB_N];
__device__ float g_lasso_part[HB_N];
__device__ int   g_lasso_cnt = 0;
__device__ __align__(16) uint16_t g_wh[HEADS*9*CIN*CPER];  // bf16 hi [h][t][c][oc]
__device__ __align__(16) uint16_t g_wl[HEADS*9*CIN*CPER];  // bf16 lo
// precomputed masked-BN planes: [hb][ck][GROW px][16 hi | 16 lo] u16
__device__ __align__(16) uint16_t g_plane[(size_t)HB_N*4*GROW*32];

// ------------------------- helpers -------------------------
__device__ __forceinline__ uint32_t smem_u32(const void* p) {
    uint32_t a;
    asm("{ .reg .u64 t; cvta.to.shared.u64 t, %1; cvt.u32.u64 %0, t; }" : "=r"(a) : "l"(p));
    return a;
}
__device__ __forceinline__ void ldsm4(uint32_t addr, uint32_t* r) {
    asm("ldmatrix.sync.aligned.m8n8.x4.shared.b16 {%0,%1,%2,%3}, [%4];"
        : "=r"(r[0]), "=r"(r[1]), "=r"(r[2]), "=r"(r[3]) : "r"(addr));
}
__device__ __forceinline__ void ldsm4t(uint32_t addr, uint32_t* r) {
    asm("ldmatrix.sync.aligned.m8n8.x4.trans.shared.b16 {%0,%1,%2,%3}, [%4];"
        : "=r"(r[0]), "=r"(r[1]), "=r"(r[2]), "=r"(r[3]) : "r"(addr));
}
__device__ __forceinline__ void mma16816(float* d, const uint32_t* a, const uint32_t* b) {
    asm("mma.sync.aligned.m16n8k16.row.col.f32.bf16.bf16.f32 "
        "{%0,%1,%2,%3}, {%4,%5,%6,%7}, {%8,%9}, {%0,%1,%2,%3};"
        : "+f"(d[0]), "+f"(d[1]), "+f"(d[2]), "+f"(d[3])
        : "r"(a[0]), "r"(a[1]), "r"(a[2]), "r"(a[3]), "r"(b[0]), "r"(b[1]));
}
__device__ __forceinline__ void cp16(uint32_t dst, const void* src) {
    asm volatile("cp.async.cg.shared.global [%0], [%1], 16;"
                 :: "r"(dst), "l"(src) : "memory");
}
__device__ __forceinline__ uint32_t pack_bf(float e, float o) {
    uint32_t r;
    asm("cvt.rn.bf16x2.f32 %0, %1, %2;" : "=r"(r) : "f"(o), "f"(e));
    return r;
}

// =====================================================================
// Kernel 0: weight bf16 hi/lo split -> [h][t][c][oc]
// =====================================================================
__global__ void wsplit_kernel(const float* __restrict__ cw)
{
    int idx = blockIdx.x*256 + threadIdx.x;
    if (idx >= HEADS*9*CIN*CPER) return;
    int oc  = idx & 63;
    int c   = (idx >> 6) & 255;
    int ht  = idx >> 14;
    int t   = ht % 9;
    int h   = ht / 9;
    float w = cw[(((size_t)(h*CPER + oc))*CIN + c)*9 + t];
    __nv_bfloat16 hi = __float2bfloat16(w);
    float hf = __bfloat162float(hi);
    __nv_bfloat16 lo = __float2bfloat16(w - hf);
    g_wh[idx] = __bfloat16_as_ushort(hi);
    g_wl[idx] = __bfloat16_as_ushort(lo);
}

// =====================================================================
// Kernel 1: BN+ReLU fused global average pool
// =====================================================================
__global__ void bn_pool_kernel(const float* __restrict__ x,
                               const float* __restrict__ gmm,
                               const float* __restrict__ bet,
                               const float* __restrict__ mea,
                               const float* __restrict__ var)
{
    int bc = blockIdx.x;
    int c  = bc & (CIN-1);
    float a  = gmm[c] * rsqrtf(var[c] + BN_EPS);
    float sh = bet[c] - mea[c] * a;
    const float4* xp = (const float4*)(x + (size_t)bc * NPIX);
    float s = 0.f;
    for (int i = threadIdx.x; i < NPIX/4; i += 256) {
        float4 v = xp[i];
        s += fmaxf(fmaf(v.x, a, sh), 0.f) + fmaxf(fmaf(v.y, a, sh), 0.f)
           + fmaxf(fmaf(v.z, a, sh), 0.f) + fmaxf(fmaf(v.w, a, sh), 0.f);
    }
    #pragma unroll
    for (int o = 16; o; o >>= 1) s += __shfl_xor_sync(0xffffffffu, s, o);
    __shared__ float r8[8];
    if ((threadIdx.x & 31) == 0) r8[threadIdx.x >> 5] = s;
    __syncthreads();
    if (threadIdx.x < 8) {
        float v = r8[threadIdx.x];
        #pragma unroll
        for (int o = 4; o; o >>= 1) v += __shfl_xor_sync(0xffu, v, o);
        if (threadIdx.x == 0) g_xavg[bc] = v * (1.f / (float)NPIX);
    }
}

// =====================================================================
// Kernel 2: SE gate + exact top-k threshold + compaction + lasso
// =====================================================================
__global__ void se_kernel(const float* __restrict__ fc1,
                          const float* __restrict__ fc2,
                          const float* __restrict__ fcb,
                          const int*   inact_p,
                          float*       lasso_out)
{
    __shared__ float sav[256];
    __shared__ float sy[16];
    __shared__ float ssort[256];
    __shared__ int   wcnt[8];
    __shared__ int   woff[9];

    int hb = blockIdx.x;
    int h  = hb >> 4, b = hb & 15;
    int tid = threadIdx.x;

    sav[tid] = g_xavg[b*CIN + tid];
    __syncthreads();

    if (tid < 16) {
        const float* w = fc1 + (h*16 + tid)*256;
        float s = 0.f;
        #pragma unroll 8
        for (int c = 0; c < 256; ++c) s = fmaf(w[c], sav[c], s);
        sy[tid] = fmaxf(s, 0.f);
    }
    __syncthreads();

    float m;
    {
        const float* w = fc2 + ((size_t)(h*256 + tid)) * 16;
        float s = fcb[h*256 + tid];
        #pragma unroll
        for (int r = 0; r < 16; ++r) s = fmaf(w[r], sy[r], s);
        m = fmaxf(s, 0.f);
    }
    ssort[tid] = m;
    __syncthreads();

    sav[tid] = m;
    __syncthreads();
    for (int st = 128; st > 0; st >>= 1) {
        if (tid < st) sav[tid] += sav[tid + st];
        __syncthreads();
    }
    if (tid == 0) {
        g_lasso_part[hb] = sav[0];
        __threadfence();
        int ticket = atomicAdd(&g_lasso_cnt, 1);
        if (ticket == HB_N - 1) {
            if (lasso_out) {
                volatile float* vp = g_lasso_part;
                float s = 0.f;
                for (int i = 0; i < HB_N; ++i) s += vp[i];
                *lasso_out = s * (1.f / (float)(BATCH*CIN));
            }
            g_lasso_cnt = 0;
        }
    }
    __syncthreads();

    for (int k = 2; k <= 256; k <<= 1) {
        for (int j = k >> 1; j > 0; j >>= 1) {
            int ixj = tid ^ j;
            if (ixj > tid) {
                float va = ssort[tid], vb = ssort[ixj];
                bool up = ((tid & k) == 0);
                if ((va > vb) == up) { ssort[tid] = vb; ssort[ixj] = va; }
            }
            __syncthreads();
        }
    }

    int inact = 192;
    if (inact_p) {
        int iv = *inact_p;
        if (iv < 0 || iv > 256) {
            float f = __int_as_float(iv);
            iv = (f >= 0.f && f <= 256.f) ? (int)(f + 0.5f) : 192;
        }
        inact = iv;
    }
    float thresh = (inact > 0) ? ssort[min(inact,256) - 1] : -1e30f;

    bool keep = (m > thresh);
    unsigned ball = __ballot_sync(0xffffffffu, keep);
    int wid = tid >> 5, lane = tid & 31;
    if (lane == 0) wcnt[wid] = __popc(ball);
    __syncthreads();
    if (tid == 0) {
        int o = 0;
        #pragma unroll
        for (int w = 0; w < 8; ++w) { woff[w] = o; o += wcnt[w]; }
        woff[8] = o;
        g_act_cnt[hb] = o;
    }
    __syncthreads();
    int total = woff[8];
    int padded = (total + 15) & ~15;
    if (tid >= total && tid < padded) {
        g_act_idx[hb*256 + tid] = 0;
        g_act_val[hb*256 + tid] = 0.f;
    }
    if (keep) {
        int slot = woff[wid] + __popc(ball & ((1u << lane) - 1));
        g_act_idx[hb*256 + slot] = tid;
        g_act_val[hb*256 + slot] = m;
    }
}

// =====================================================================
// Kernel 2b: xprep — precompute masked-BN bf16 hi/lo planes to gmem.
//  grid (14, 4, 64): (px segment, chunk, hb). Row = [16 hi][16 lo] u16.
// =====================================================================
__global__ void xprep_kernel(const float* __restrict__ x,
                             const float* __restrict__ gmm,
                             const float* __restrict__ bet,
                             const float* __restrict__ mea,
                             const float* __restrict__ var)
{
    int hb = blockIdx.z, ck = blockIdx.y;
    int cnt = g_act_cnt[hb];
    if (ck >= ((cnt + 15) >> 4)) return;
    int h = hb >> 4, b = hb & 15;
    (void)h;

    __shared__ int   sch[16];
    __shared__ float sca[16], scb[16], scm[16];
    int tid = threadIdx.x;
    if (tid < 16) {
        int pos = ck*16 + tid;
        int ch = 0; float mv = 0.f;
        if (pos < cnt) { ch = g_act_idx[hb*256 + pos]; mv = g_act_val[hb*256 + pos]; }
        float a = gmm[ch] * rsqrtf(var[ch] + BN_EPS);
        sch[tid] = ch; sca[tid] = a;
        scb[tid] = bet[ch] - mea[ch] * a; scm[tid] = mv;
    }
    __syncthreads();

    int px64 = blockIdx.x*256 + tid;
    if (px64 >= GROW) return;
    int pg = px64 - 64;
    bool xin = false; size_t xoff = 0;
    if (pg >= 0 && pg < PTOT) {
        int rp = pg / PGRID, cp = pg - rp*PGRID;
        int rr = rp - 1, cc = cp - 1;
        if ((unsigned)rr < (unsigned)HH && (unsigned)cc < (unsigned)WW) {
            xin = true; xoff = (size_t)rr*WW + cc;
        }
    }
    uint32_t row[16];
    if (xin) {
        const float* xb = x + (size_t)b*CIN*NPIX;
        float xv[16];
        #pragma unroll
        for (int ic = 0; ic < 16; ++ic) xv[ic] = xb[(size_t)sch[ic]*NPIX + xoff];
        #pragma unroll
        for (int j = 0; j < 8; ++j) {
            int ic = j*2;
            float v0 = fmaxf(fmaf(xv[ic],   sca[ic],   scb[ic]),   0.f) * scm[ic];
            float v1 = fmaxf(fmaf(xv[ic+1], sca[ic+1], scb[ic+1]), 0.f) * scm[ic+1];
            uint32_t hp = pack_bf(v0, v1);
            float h0 = __uint_as_float(hp << 16);
            float h1 = __uint_as_float(hp & 0xffff0000u);
            row[j]   = hp;
            row[8+j] = pack_bf(v0 - h0, v1 - h1);
        }
    } else {
        #pragma unroll
        for (int j = 0; j < 16; ++j) row[j] = 0u;
    }
    uint4* dst = (uint4*)(g_plane + (((size_t)hb*4 + ck)*GROW + px64)*32);
    dst[0] = make_uint4(row[0],  row[1],  row[2],  row[3]);
    dst[1] = make_uint4(row[4],  row[5],  row[6],  row[7]);
    dst[2] = make_uint4(row[8],  row[9],  row[10], row[11]);
    dst[3] = make_uint4(row[12], row[13], row[14], row[15]);
}

// =====================================================================
// conv staging: one cp.async group per chunk (weights swizzled + plane)
// =====================================================================
__device__ __forceinline__ void stage_sch(int* schA, int slot, int ckbase,
                                          int cnt, int hb, int tid)
{
    if (tid < 16) {
        int pos = ckbase + tid;
        schA[slot*16 + tid] = (pos < cnt) ? g_act_idx[hb*256 + pos] : 0;
    }
}

__device__ __forceinline__ void issue_chunk(
    const int* sch16, int ck, int buf, uint32_t smb, int hb, int q0,
    const uint16_t* whBase, const uint16_t* wlBase, int tid)
{
    uint32_t wdst = smb + (buf ? OFF_W1H : OFF_W0H);
    #pragma unroll
    for (int i = 0; i < 9; ++i) {
        int idx = tid + i*256;                 // 0..2303
        int arr = idx >= 1152;
        int r2  = idx - arr*1152;
        int row = r2 >> 3;                     // t*16+ic (0..143)
        int seg = r2 & 7;
        int ic  = row & 15, t = row >> 4;
        const uint16_t* src = (arr ? wlBase : whBase)
                            + (((t*CIN + sch16[ic]) << 6) + seg*8);
        cp16(wdst + (uint32_t)(arr*WTILE_B + row*128 + ((seg<<4) ^ ((row&7)<<4))), src);
    }
    uint32_t pdst = smb + (buf ? OFF_P1 : OFF_P0);
    const uint16_t* gp = g_plane + (((size_t)hb*4 + ck)*GROW + (5 + q0))*32;
    #pragma unroll
    for (int i = 0; i < 4; ++i) {
        int idx = tid + i*256;                 // 0..983 valid
        if (idx < 984) {
            int p = idx >> 2, seg = idx & 3;
            cp16(pdst + (uint32_t)(p*80 + seg*16), gp + (size_t)p*32 + seg*8);
        }
    }
    asm volatile("cp.async.commit_group;" ::: "memory");
}

// =====================================================================
// Kernel 3: sparse grouped conv; fully cp.async-fed mma pipeline.
// =====================================================================
__global__ __launch_bounds__(256, 2)
void conv_mma_kernel(float* __restrict__ out)
{
    extern __shared__ __align__(16) char dsm[];
    int* schA = (int*)(dsm + OFF_C);           // [2][16]

    int tid  = threadIdx.x;
    int wid  = tid >> 5, lane = tid & 31;
    int wm   = wid >> 1, wn = wid & 1;
    int grp  = lane >> 2, qd = lane & 3;

    int hb = blockIdx.y;
    int h  = hb >> 4, b = hb & 15;
    int q0 = blockIdx.x * 128;

    int cnt = g_act_cnt[hb];
    int nchunks = (cnt + 15) >> 4;

    float d[2][4][4];
    #pragma unroll
    for (int mi = 0; mi < 2; ++mi)
        #pragma unroll
        for (int ni = 0; ni < 4; ++ni)
            #pragma unroll
            for (int k = 0; k < 4; ++k) d[mi][ni][k] = 0.f;

    uint32_t smb = smem_u32(dsm);
    // A ldsm lane offset within plane buffer (pitch 80, hi at +0, lo at +32)
    uint32_t aOff = (uint32_t)((59 + wm*32 + (lane & 15))*80 + ((lane >> 4) << 4));
    // B ldsm lane offsets (128B rows, 16B XOR swizzle)
    uint32_t bc0 = (uint32_t)(wn*64 + ((lane >> 4) << 4));
    uint32_t swB0 = (uint32_t)((lane & 15)*128) + (bc0 ^ (uint32_t)((lane & 7) << 4));
    uint32_t swB1 = swB0 ^ 32u;

    const uint16_t* whBase = g_wh + ((size_t)h*9*CIN << 6);
    const uint16_t* wlBase = g_wl + ((size_t)h*9*CIN << 6);

    // ---- prologue
    stage_sch(schA, 0, 0, cnt, hb, tid);
    __syncthreads();
    if (nchunks > 0)
        issue_chunk(schA, 0, 0, smb, hb, q0, whBase, wlBase, tid);
    if (nchunks > 1)
        stage_sch(schA, 1, 16, cnt, hb, tid);
    __syncthreads();

    #pragma unroll 1
    for (int ck = 0; ck < nchunks; ++ck) {
        int buf = ck & 1;

        if (ck + 1 < nchunks) {
            issue_chunk(schA + (buf^1)*16, ck+1, buf^1, smb, hb, q0, whBase, wlBase, tid);
            asm volatile("cp.async.wait_group 1;" ::: "memory");
        } else {
            asm volatile("cp.async.wait_group 0;" ::: "memory");
        }
        if (ck + 2 < nchunks)
            stage_sch(schA, buf, (ck+2)*16, cnt, hb, tid);
        __syncthreads();   // chunk ck data visible everywhere

        uint32_t pA = smb + (buf ? OFF_P1 : OFF_P0) + aOff;
        uint32_t pB = smb + (buf ? OFF_W1H : OFF_W0H);
        #pragma unroll
        for (int t = 0; t < 9; ++t) {
            int ky = t / 3, kx = t - ky*3;
            int sb = ((ky - 1)*PGRID + (kx - 1)) * 80;

            uint32_t ah[2][4], al[2][4];
            ldsm4((uint32_t)(pA + sb),          ah[0]);
            ldsm4((uint32_t)(pA + sb + 1280),   ah[1]);
            ldsm4((uint32_t)(pA + sb + 32),     al[0]);
            ldsm4((uint32_t)(pA + sb + 32 + 1280), al[1]);

            uint32_t bh[4][2], bl[4][2];
            uint32_t wb = pB + (uint32_t)(t*2048);
            ldsm4t(wb + swB0,            &bh[0][0]);
            ldsm4t(wb + swB1,            &bh[2][0]);
            ldsm4t(wb + WTILE_B + swB0,  &bl[0][0]);
            ldsm4t(wb + WTILE_B + swB1,  &bl[2][0]);

            #pragma unroll
            for (int mi = 0; mi < 2; ++mi)
                #pragma unroll
                for (int ni = 0; ni < 4; ++ni) {
                    mma16816(d[mi][ni], ah[mi], bh[ni]);
                    mma16816(d[mi][ni], ah[mi], bl[ni]);
                    mma16816(d[mi][ni], al[mi], bh[ni]);
                }
        }
        __syncthreads();   // protect buf before next iteration's issue overwrites it
    }

    // ---- epilogue
    #pragma unroll
    for (int mi = 0; mi < 2; ++mi) {
        #pragma unroll
        for (int dr = 0; dr < 2; ++dr) {
            int row = wm*32 + mi*16 + dr*8 + grp;
            int q   = q0 + row;
            int rp2 = q / PGRID, cp2 = q - rp2*PGRID;
            bool v = (rp2 >= 1) && (rp2 <= HH) && (cp2 >= 1) && (cp2 <= WW);
            if (v) {
                size_t ob = ((size_t)b*(HEADS*CPER) + h)*NPIX
                          + (size_t)(rp2-1)*WW + (cp2-1);
                #pragma unroll
                for (int ni = 0; ni < 4; ++ni) {
                    int oc = wn*32 + ni*8 + qd*2;
                    out[ob + (size_t)(oc*HEADS)*NPIX]     = d[mi][ni][dr*2 + 0];
                    out[ob + (size_t)((oc+1)*HEADS)*NPIX] = d[mi][ni][dr*2 + 1];
                }
            }
        }
    }
}

// =====================================================================
extern "C" void kernel_launch(void* const* d_in, const int* in_sizes, int n_in,
                              void* d_out, int out_size)
{
    const float* x    = (const float*)d_in[0];
    const float* gmm  = (const float*)d_in[1];
    const float* bet  = (const float*)d_in[2];
    const float* mea  = (const float*)d_in[3];
    const float* var  = (const float*)d_in[4];
    const float* fc1  = (const float*)d_in[5];
    const float* fc2  = (const float*)d_in[6];
    const float* fcb  = (const float*)d_in[7];
    const float* cw   = (const float*)d_in[8];
    const int*   inact = (n_in > 9) ? (const int*)d_in[9] : nullptr;
    float* out = (float*)d_out;
    float* lasso_out = (out_size > NOUT) ? (out + NOUT) : nullptr;

    bn_pool_kernel<<<BATCH*CIN, 256>>>(x, gmm, bet, mea, var);
    wsplit_kernel<<<(HEADS*9*CIN*CPER + 255)/256, 256>>>(cw);
    se_kernel<<<HB_N, 256>>>(fc1, fc2, fcb, inact, lasso_out);
    xprep_kernel<<<dim3(14, 4, HB_N), 256>>>(x, gmm, bet, mea, var);

    cudaFuncSetAttribute(conv_mma_kernel, cudaFuncAttributeMaxDynamicSharedMemorySize,
                         SMEM_BYTES);
    dim3 grid(NTILES, HB_N);
    conv_mma_kernel<<<grid, 256, SMEM_BYTES>>>(out);
}

// round 12
// speedup vs baseline: 1.1304x; 1.1304x over previous
#include <cuda_runtime.h>
#include <cuda_bf16.h>
#include <math.h>
#include <stdint.h>

#define BATCH   16
#define CIN     256
#define HH      56
#define WW      56
#define HEADS   4
#define CPER    64
#define HB_N    64
#define NPIX    3136
#define NOUT    (BATCH*HEADS*CPER*NPIX)
#define BN_EPS  1e-5f

#define PGRID   58
#define PTOT    (PGRID*PGRID)
#define NTILES  26
#define PLROWS  246
#define PITCH_P 24               // bf16 per plane row (16 ic + 8 pad; 48B rows)
#define PITCH_W 72               // bf16 per weight row (144B rows)

// dynamic smem byte offsets
#define WBYTES   20736           // 144 rows * 144 B
#define OFF_W0H  0
#define OFF_W0L  20736
#define OFF_W1H  41472
#define OFF_W1L  62208
#define OFF_PH   82944           // 246*48 = 11808
#define OFF_PL   94752
#define OFF_C    106560          // sch[2][16], sca[2][16], scb[2][16], scm[2][16]
#define SMEM_BYTES 107072

__device__ float g_xavg[BATCH*CIN];
__device__ int   g_act_idx[HB_N*256];
__device__ float g_act_val[HB_N*256];
__device__ int   g_act_cnt[HB_N];
__device__ float g_lasso_part[HB_N];
__device__ int   g_lasso_cnt = 0;
__device__ __align__(16) uint16_t g_wh[HEADS*9*CIN*CPER];  // bf16 hi, [h][t][c][oc]
__device__ __align__(16) uint16_t g_wl[HEADS*9*CIN*CPER];  // bf16 lo

// ------------------------- helpers -------------------------
__device__ __forceinline__ uint32_t smem_u32(const void* p) {
    uint32_t a;
    asm("{ .reg .u64 t; cvta.to.shared.u64 t, %1; cvt.u32.u64 %0, t; }" : "=r"(a) : "l"(p));
    return a;
}
__device__ __forceinline__ void ldsm4(uint32_t addr, uint32_t* r) {
    asm("ldmatrix.sync.aligned.m8n8.x4.shared.b16 {%0,%1,%2,%3}, [%4];"
        : "=r"(r[0]), "=r"(r[1]), "=r"(r[2]), "=r"(r[3]) : "r"(addr));
}
__device__ __forceinline__ void ldsm4t(uint32_t addr, uint32_t* r) {
    asm("ldmatrix.sync.aligned.m8n8.x4.trans.shared.b16 {%0,%1,%2,%3}, [%4];"
        : "=r"(r[0]), "=r"(r[1]), "=r"(r[2]), "=r"(r[3]) : "r"(addr));
}
__device__ __forceinline__ void mma16816(float* d, const uint32_t* a, const uint32_t* b) {
    asm("mma.sync.aligned.m16n8k16.row.col.f32.bf16.bf16.f32 "
        "{%0,%1,%2,%3}, {%4,%5,%6,%7}, {%8,%9}, {%0,%1,%2,%3};"
        : "+f"(d[0]), "+f"(d[1]), "+f"(d[2]), "+f"(d[3])
        : "r"(a[0]), "r"(a[1]), "r"(a[2]), "r"(a[3]), "r"(b[0]), "r"(b[1]));
}
__device__ __forceinline__ void cp16(uint32_t dst, const void* src) {
    asm volatile("cp.async.cg.shared.global [%0], [%1], 16;"
                 :: "r"(dst), "l"(src) : "memory");
}
__device__ __forceinline__ uint32_t pack_bf(float e, float o) {
    uint32_t r;
    asm("cvt.rn.bf16x2.f32 %0, %1, %2;" : "=r"(r) : "f"(o), "f"(e));
    return r;
}

// =====================================================================
// Kernel 0: weight bf16 hi/lo split -> [h][t][c][oc]
// =====================================================================
__global__ void wsplit_kernel(const float* __restrict__ cw)
{
    int idx = blockIdx.x*256 + threadIdx.x;
    if (idx >= HEADS*9*CIN*CPER) return;
    int oc  = idx & 63;
    int c   = (idx >> 6) & 255;
    int ht  = idx >> 14;
    int t   = ht % 9;
    int h   = ht / 9;
    float w = cw[(((size_t)(h*CPER + oc))*CIN + c)*9 + t];
    __nv_bfloat16 hi = __float2bfloat16(w);
    float hf = __bfloat162float(hi);
    __nv_bfloat16 lo = __float2bfloat16(w - hf);
    g_wh[idx] = __bfloat16_as_ushort(hi);
    g_wl[idx] = __bfloat16_as_ushort(lo);
}

// =====================================================================
// Kernel 1: BN+ReLU fused global average pool (float4 + shfl reduce)
// =====================================================================
__global__ void bn_pool_kernel(const float* __restrict__ x,
                               const float* __restrict__ gmm,
                               const float* __restrict__ bet,
                               const float* __restrict__ mea,
                               const float* __restrict__ var)
{
    int bc = blockIdx.x;
    int c  = bc & (CIN-1);
    float a  = gmm[c] * rsqrtf(var[c] + BN_EPS);
    float sh = bet[c] - mea[c] * a;
    const float4* xp = (const float4*)(x + (size_t)bc * NPIX);
    float s = 0.f;
    for (int i = threadIdx.x; i < NPIX/4; i += 256) {
        float4 v = xp[i];
        s += fmaxf(fmaf(v.x, a, sh), 0.f) + fmaxf(fmaf(v.y, a, sh), 0.f)
           + fmaxf(fmaf(v.z, a, sh), 0.f) + fmaxf(fmaf(v.w, a, sh), 0.f);
    }
    #pragma unroll
    for (int o = 16; o; o >>= 1) s += __shfl_xor_sync(0xffffffffu, s, o);
    __shared__ float r8[8];
    if ((threadIdx.x & 31) == 0) r8[threadIdx.x >> 5] = s;
    __syncthreads();
    if (threadIdx.x < 8) {
        float v = r8[threadIdx.x];
        #pragma unroll
        for (int o = 4; o; o >>= 1) v += __shfl_xor_sync(0xffu, v, o);
        if (threadIdx.x == 0) g_xavg[bc] = v * (1.f / (float)NPIX);
    }
}

// =====================================================================
// Kernel 2: SE gate + exact top-k threshold + compaction + lasso
// =====================================================================
__global__ void se_kernel(const float* __restrict__ fc1,
                          const float* __restrict__ fc2,
                          const float* __restrict__ fcb,
                          const int*   inact_p,
                          float*       lasso_out)
{
    __shared__ float sav[256];
    __shared__ float sy[16];
    __shared__ float ssort[256];
    __shared__ int   wcnt[8];
    __shared__ int   woff[9];

    int hb = blockIdx.x;
    int h  = hb >> 4, b = hb & 15;
    int tid = threadIdx.x;

    sav[tid] = g_xavg[b*CIN + tid];
    __syncthreads();

    if (tid < 16) {
        const float* w = fc1 + (h*16 + tid)*256;
        float s = 0.f;
        #pragma unroll 8
        for (int c = 0; c < 256; ++c) s = fmaf(w[c], sav[c], s);
        sy[tid] = fmaxf(s, 0.f);
    }
    __syncthreads();

    float m;
    {
        const float* w = fc2 + ((size_t)(h*256 + tid)) * 16;
        float s = fcb[h*256 + tid];
        #pragma unroll
        for (int r = 0; r < 16; ++r) s = fmaf(w[r], sy[r], s);
        m = fmaxf(s, 0.f);
    }
    ssort[tid] = m;
    __syncthreads();

    sav[tid] = m;
    __syncthreads();
    for (int st = 128; st > 0; st >>= 1) {
        if (tid < st) sav[tid] += sav[tid + st];
        __syncthreads();
    }
    if (tid == 0) {
        g_lasso_part[hb] = sav[0];
        __threadfence();
        int ticket = atomicAdd(&g_lasso_cnt, 1);
        if (ticket == HB_N - 1) {
            if (lasso_out) {
                volatile float* vp = g_lasso_part;
                float s = 0.f;
                for (int i = 0; i < HB_N; ++i) s += vp[i];
                *lasso_out = s * (1.f / (float)(BATCH*CIN));
            }
            g_lasso_cnt = 0;   // self-reset for next replay
        }
    }
    __syncthreads();

    for (int k = 2; k <= 256; k <<= 1) {
        for (int j = k >> 1; j > 0; j >>= 1) {
            int ixj = tid ^ j;
            if (ixj > tid) {
                float va = ssort[tid], vb = ssort[ixj];
                bool up = ((tid & k) == 0);
                if ((va > vb) == up) { ssort[tid] = vb; ssort[ixj] = va; }
            }
            __syncthreads();
        }
    }

    int inact = 192;
    if (inact_p) {
        int iv = *inact_p;
        if (iv < 0 || iv > 256) {
            float f = __int_as_float(iv);
            iv = (f >= 0.f && f <= 256.f) ? (int)(f + 0.5f) : 192;
        }
        inact = iv;
    }
    float thresh = (inact > 0) ? ssort[min(inact,256) - 1] : -1e30f;

    bool keep = (m > thresh);
    unsigned ball = __ballot_sync(0xffffffffu, keep);
    int wid = tid >> 5, lane = tid & 31;
    if (lane == 0) wcnt[wid] = __popc(ball);
    __syncthreads();
    if (tid == 0) {
        int o = 0;
        #pragma unroll
        for (int w = 0; w < 8; ++w) { woff[w] = o; o += wcnt[w]; }
        woff[8] = o;
        g_act_cnt[hb] = o;
    }
    __syncthreads();
    int total = woff[8];
    int padded = (total + 15) & ~15;
    if (tid >= total && tid < padded) {
        g_act_idx[hb*256 + tid] = 0;
        g_act_val[hb*256 + tid] = 0.f;
    }
    if (keep) {
        int slot = woff[wid] + __popc(ball & ((1u << lane) - 1));
        g_act_idx[hb*256 + slot] = tid;
        g_act_val[hb*256 + slot] = m;
    }
}

// =====================================================================
// conv staging helpers
// =====================================================================
struct ConstView { int* sch; float* sca; float* scb; float* scm; };

__device__ __forceinline__ void stage_consts(
    ConstView cv, int slot, int ckbase, int cnt, int hb, int tid,
    const float* gmm, const float* bet, const float* mea, const float* var)
{
    if (tid < 16) {
        int pos = ckbase + tid;
        int ch = 0; float mv = 0.f;
        if (pos < cnt) { ch = g_act_idx[hb*256 + pos]; mv = g_act_val[hb*256 + pos]; }
        float a  = gmm[ch] * rsqrtf(var[ch] + BN_EPS);
        cv.sch[slot*16 + tid] = ch;
        cv.sca[slot*16 + tid] = a;
        cv.scb[slot*16 + tid] = bet[ch] - mea[ch] * a;
        cv.scm[slot*16 + tid] = mv;
    }
}

// full (non-prefetched) plane staging — used in prologue only
__device__ __forceinline__ void stage_plane(
    ConstView cv, int cs, const float* __restrict__ xb, bool xin, size_t xoff,
    __nv_bfloat16* pH, __nv_bfloat16* pL, int tid)
{
    if (tid >= PLROWS) return;
    if (!xin) {
        #pragma unroll
        for (int j = 0; j < 16; j += 2) {
            int eo = tid*PITCH_P + j;
            *(uint32_t*)&pH[eo] = 0u;
            *(uint32_t*)&pL[eo] = 0u;
        }
        return;
    }
    #pragma unroll
    for (int g = 0; g < 2; ++g) {
        float xv[8];
        #pragma unroll
        for (int j = 0; j < 8; ++j) {
            int ic = cs + g*8 + j;
            xv[j] = xb[(size_t)cv.sch[ic]*NPIX + xoff];
        }
        #pragma unroll
        for (int j = 0; j < 8; j += 2) {
            int ic = cs + g*8 + j;
            float v0 = fmaxf(fmaf(xv[j],   cv.sca[ic],   cv.scb[ic]),   0.f) * cv.scm[ic];
            float v1 = fmaxf(fmaf(xv[j+1], cv.sca[ic+1], cv.scb[ic+1]), 0.f) * cv.scm[ic+1];
            uint32_t hp = pack_bf(v0, v1);
            float h0 = __uint_as_float(hp << 16);
            float h1 = __uint_as_float(hp & 0xffff0000u);
            uint32_t lp = pack_bf(v0 - h0, v1 - h1);
            int eo = tid*PITCH_P + g*8 + j;
            *(uint32_t*)&pH[eo] = hp;
            *(uint32_t*)&pL[eo] = lp;
        }
    }
}

// cvt+STS from prefetched registers
__device__ __forceinline__ void store_plane_regs(
    ConstView cv, int cs, const float* pf, bool xin,
    __nv_bfloat16* pH, __nv_bfloat16* pL, int tid)
{
    if (tid >= PLROWS) return;
    if (!xin) {
        #pragma unroll
        for (int j = 0; j < 16; j += 2) {
            int eo = tid*PITCH_P + j;
            *(uint32_t*)&pH[eo] = 0u;
            *(uint32_t*)&pL[eo] = 0u;
        }
        return;
    }
    #pragma unroll
    for (int j = 0; j < 16; j += 2) {
        int ic = cs + j;
        float v0 = fmaxf(fmaf(pf[j],   cv.sca[ic],   cv.scb[ic]),   0.f) * cv.scm[ic];
        float v1 = fmaxf(fmaf(pf[j+1], cv.sca[ic+1], cv.scb[ic+1]), 0.f) * cv.scm[ic+1];
        uint32_t hp = pack_bf(v0, v1);
        float h0 = __uint_as_float(hp << 16);
        float h1 = __uint_as_float(hp & 0xffff0000u);
        uint32_t lp = pack_bf(v0 - h0, v1 - h1);
        int eo = tid*PITCH_P + j;
        *(uint32_t*)&pH[eo] = hp;
        *(uint32_t*)&pL[eo] = lp;
    }
}

__device__ __forceinline__ void issue_weights(
    ConstView cv, int slot, uint32_t wdst,
    const uint16_t* whBase, const uint16_t* wlBase, int tid)
{
    #pragma unroll
    for (int i = 0; i < 9; ++i) {
        int idx = tid + i*256;                  // 0..2303
        int arr = idx >= 1152;
        int r   = idx - arr*1152;
        int row = r >> 3;                       // t*16+ic
        int seg = r & 7;
        int ic  = row & 15, t = row >> 4;
        const uint16_t* src = (arr ? wlBase : whBase)
                            + (((t*CIN + cv.sch[slot*16 + ic]) << 6) + seg*8);
        cp16(wdst + (uint32_t)(arr*WBYTES + row*144 + seg*16), src);
    }
    asm volatile("cp.async.commit_group;" ::: "memory");
}

// one conv tap: ldsm + 12 mma
#define TAP_BODY(t)                                                          \
    {                                                                        \
        int ky = (t) / 3, kx = (t) - ky*3;                                   \
        int sb = ((ky - 1)*PGRID + (kx - 1)) * 48;                           \
        uint32_t ah[2][4], al[2][4];                                         \
        ldsm4((uint32_t)(aH0 + sb),       ah[0]);                            \
        ldsm4((uint32_t)(aH0 + sb + 768), ah[1]);                            \
        ldsm4((uint32_t)(aL0 + sb),       al[0]);                            \
        ldsm4((uint32_t)(aL0 + sb + 768), al[1]);                            \
        uint32_t bh[4][2], bl[4][2];                                         \
        uint32_t bb = bBase + (uint32_t)((t)*2304);                          \
        ldsm4t(bb,                 &bh[0][0]);                               \
        ldsm4t(bb + 32,            &bh[2][0]);                               \
        ldsm4t(bb + WBYTES,        &bl[0][0]);                               \
        ldsm4t(bb + WBYTES + 32,   &bl[2][0]);                               \
        _Pragma("unroll")                                                    \
        for (int mi = 0; mi < 2; ++mi)                                       \
            _Pragma("unroll")                                                \
            for (int ni = 0; ni < 4; ++ni) {                                 \
                mma16816(d[mi][ni], ah[mi], bh[ni]);                         \
                mma16816(d[mi][ni], ah[mi], bl[ni]);                         \
                mma16816(d[mi][ni], al[mi], bh[ni]);                         \
            }                                                                \
    }

// =====================================================================
// Kernel 3: sparse grouped conv via mma.sync bf16 3-pass,
//  ldmatrix.x4 fragments, cp.async weights, register-prefetched plane.
// =====================================================================
__global__ __launch_bounds__(256, 2)
void conv_mma_kernel(const float* __restrict__ x,
                     const float* __restrict__ gmm,
                     const float* __restrict__ bet,
                     const float* __restrict__ mea,
                     const float* __restrict__ var,
                     float* __restrict__ out)
{
    extern __shared__ __align__(16) char dsm[];
    __nv_bfloat16* pH = (__nv_bfloat16*)(dsm + OFF_PH);
    __nv_bfloat16* pL = (__nv_bfloat16*)(dsm + OFF_PL);
    ConstView cv;
    cv.sch = (int*)(dsm + OFF_C);
    cv.sca = (float*)(dsm + OFF_C + 128);
    cv.scb = (float*)(dsm + OFF_C + 256);
    cv.scm = (float*)(dsm + OFF_C + 384);

    int tid  = threadIdx.x;
    int wid  = tid >> 5, lane = tid & 31;
    int wm   = wid >> 1, wn = wid & 1;
    int grp  = lane >> 2, qd = lane & 3;

    int hb = blockIdx.y;
    int h  = hb >> 4, b = hb & 15;
    int q0 = blockIdx.x * 128;

    // staging pixel mapping (row p = tid)
    int pg = q0 - 59 + tid;
    bool pin = (tid < PLROWS) && (pg >= 0) && (pg < PTOT);
    int rp = pg / PGRID, cp = pg - rp*PGRID;
    int rr = rp - 1, cc = cp - 1;
    bool xin = pin && ((unsigned)rr < (unsigned)HH) && ((unsigned)cc < (unsigned)WW);
    size_t xoff = (size_t)rr*WW + cc;
    const float* xb = x + (size_t)b*CIN*NPIX;

    int cnt = g_act_cnt[hb];
    int nchunks = (cnt + 15) >> 4;

    float d[2][4][4];
    #pragma unroll
    for (int mi = 0; mi < 2; ++mi)
        #pragma unroll
        for (int ni = 0; ni < 4; ++ni)
            #pragma unroll
            for (int k = 0; k < 4; ++k) d[mi][ni][k] = 0.f;

    uint32_t smb = smem_u32(dsm);
    int aRowB = (59 + wm*32 + (lane & 15))*48 + ((lane >> 4) << 4);
    int aH0 = (int)(smb + OFF_PH) + aRowB;
    int aL0 = (int)(smb + OFF_PL) + aRowB;
    uint32_t bLane = (uint32_t)((lane & 15)*144 + wn*64 + ((lane >> 4) << 4));

    const uint16_t* whBase = g_wh + ((size_t)h*9*CIN << 6);
    const uint16_t* wlBase = g_wl + ((size_t)h*9*CIN << 6);

    // ---- prologue
    stage_consts(cv, 0, 0, cnt, hb, tid, gmm, bet, mea, var);
    __syncthreads();
    issue_weights(cv, 0, smb + OFF_W0H, whBase, wlBase, tid);
    stage_plane(cv, 0, xb, xin, xoff, pH, pL, tid);
    if (nchunks > 1)
        stage_consts(cv, 1, 16, cnt, hb, tid, gmm, bet, mea, var);
    __syncthreads();

    #pragma unroll 1
    for (int ck = 0; ck < nchunks; ++ck) {
        int buf = ck & 1;

        // ---- weights for ck+1 into other buffer; wait for ck
        if (ck + 1 < nchunks) {
            int ns = (ck + 1) & 1;
            issue_weights(cv, ns, smb + (ns ? OFF_W1H : OFF_W0H), whBase, wlBase, tid);
            asm volatile("cp.async.wait_group 1;" ::: "memory");
        } else {
            asm volatile("cp.async.wait_group 0;" ::: "memory");
        }
        __syncthreads();   // B1: weights ck + plane ck (+consts ck+1) visible

        // consts for ck+2 (slot buf is dead)
        if (ck + 2 < nchunks)
            stage_consts(cv, buf, (ck+2)*16, cnt, hb, tid, gmm, bet, mea, var);

        bool dopf = (ck + 1 < nchunks) && xin;
        int csN = (buf^1)*16;                  // consts slot for ck+1
        float pf[16];

        // prefetch batch A (8 plane LDGs for chunk ck+1)
        if (dopf) {
            #pragma unroll
            for (int j = 0; j < 8; ++j)
                pf[j] = xb[(size_t)cv.sch[csN + j]*NPIX + xoff];
        }

        // ---- compute chunk ck
        uint32_t bBase = smb + (buf ? OFF_W1H : OFF_W0H) + bLane;
        TAP_BODY(0) TAP_BODY(1) TAP_BODY(2) TAP_BODY(3) TAP_BODY(4)

        // prefetch batch B
        if (dopf) {
            #pragma unroll
            for (int j = 0; j < 8; ++j)
                pf[8+j] = xb[(size_t)cv.sch[csN + 8 + j]*NPIX + xoff];
        }

        TAP_BODY(5) TAP_BODY(6) TAP_BODY(7) TAP_BODY(8)

        // ---- store plane ck+1 from registers (single plane buffer)
        if (ck + 1 < nchunks) {
            __syncthreads();  // B2: compute done reading plane
            store_plane_regs(cv, csN, pf, xin, pH, pL, tid);
        }
    }

    // ---- epilogue
    #pragma unroll
    for (int mi = 0; mi < 2; ++mi) {
        #pragma unroll
        for (int dr = 0; dr < 2; ++dr) {
            int row = wm*32 + mi*16 + dr*8 + grp;
            int q   = q0 + row;
            int rp2 = q / PGRID, cp2 = q - rp2*PGRID;
            bool v = (rp2 >= 1) && (rp2 <= HH) && (cp2 >= 1) && (cp2 <= WW);
            if (v) {
                size_t ob = ((size_t)b*(HEADS*CPER) + h)*NPIX
                          + (size_t)(rp2-1)*WW + (cp2-1);
                #pragma unroll
                for (int ni = 0; ni < 4; ++ni) {
                    int oc = wn*32 + ni*8 + qd*2;
                    out[ob + (size_t)(oc*HEADS)*NPIX]     = d[mi][ni][dr*2 + 0];
                    out[ob + (size_t)((oc+1)*HEADS)*NPIX] = d[mi][ni][dr*2 + 1];
                }
            }
        }
    }
}

// =====================================================================
extern "C" void kernel_launch(void* const* d_in, const int* in_sizes, int n_in,
                              void* d_out, int out_size)
{
    const float* x    = (const float*)d_in[0];
    const float* gmm  = (const float*)d_in[1];
    const float* bet  = (const float*)d_in[2];
    const float* mea  = (const float*)d_in[3];
    const float* var  = (const float*)d_in[4];
    const float* fc1  = (const float*)d_in[5];
    const float* fc2  = (const float*)d_in[6];
    const float* fcb  = (const float*)d_in[7];
    const float* cw   = (const float*)d_in[8];
    const int*   inact = (n_in > 9) ? (const int*)d_in[9] : nullptr;
    float* out = (float*)d_out;
    float* lasso_out = (out_size > NOUT) ? (out + NOUT) : nullptr;

    bn_pool_kernel<<<BATCH*CIN, 256>>>(x, gmm, bet, mea, var);
    wsplit_kernel<<<(HEADS*9*CIN*CPER + 255)/256, 256>>>(cw);
    se_kernel<<<HB_N, 256>>>(fc1, fc2, fcb, inact, lasso_out);

    cudaFuncSetAttribute(conv_mma_kernel, cudaFuncAttributeMaxDynamicSharedMemorySize,
                         SMEM_BYTES);
    dim3 grid(NTILES, HB_N);
    conv_mma_kernel<<<grid, 256, SMEM_BYTES>>>(x, gmm, bet, mea, var, out);
}

// round 14
// speedup vs baseline: 1.1574x; 1.0239x over previous
#include <cuda_runtime.h>
#include <cuda_bf16.h>
#include <math.h>
#include <stdint.h>

#define BATCH   16
#define CIN     256
#define HH      56
#define WW      56
#define HEADS   4
#define CPER    64
#define HB_N    64
#define NPIX    3136
#define NOUT    (BATCH*HEADS*CPER*NPIX)
#define BN_EPS  1e-5f

#define PGRID   58
#define PTOT    (PGRID*PGRID)
#define NTILES  26
#define PLROWS  246
#define PITCH_PB 80              // bytes per plane row: [16 hi|16 lo|16 pad]

// dynamic smem byte offsets
#define WTILE_B  18432           // 144 rows * 128 B (XOR-swizzled)
#define OFF_W0H  0
#define OFF_W0L  18432
#define OFF_W1H  36864
#define OFF_W1L  55296
#define OFF_P0   73728           // 246*80 = 19680
#define OFF_P1   93408
#define OFF_C    113088          // sch[2][16], sca[2][16], scb[2][16], scm[2][16]
#define SMEM_BYTES 113600

__device__ float g_xavg[BATCH*CIN];
__device__ int   g_act_idx[HB_N*256];
__device__ float g_act_val[HB_N*256];
__device__ int   g_act_cnt[HB_N];
__device__ float g_lasso_part[HB_N];
__device__ int   g_lasso_cnt = 0;
__device__ __align__(16) uint16_t g_wh[HEADS*9*CIN*CPER];  // bf16 hi, [h][t][c][oc]
__device__ __align__(16) uint16_t g_wl[HEADS*9*CIN*CPER];  // bf16 lo

// ------------------------- helpers -------------------------
__device__ __forceinline__ uint32_t smem_u32(const void* p) {
    uint32_t a;
    asm("{ .reg .u64 t; cvta.to.shared.u64 t, %1; cvt.u32.u64 %0, t; }" : "=r"(a) : "l"(p));
    return a;
}
__device__ __forceinline__ void ldsm4(uint32_t addr, uint32_t* r) {
    asm("ldmatrix.sync.aligned.m8n8.x4.shared.b16 {%0,%1,%2,%3}, [%4];"
        : "=r"(r[0]), "=r"(r[1]), "=r"(r[2]), "=r"(r[3]) : "r"(addr));
}
__device__ __forceinline__ void ldsm4t(uint32_t addr, uint32_t* r) {
    asm("ldmatrix.sync.aligned.m8n8.x4.trans.shared.b16 {%0,%1,%2,%3}, [%4];"
        : "=r"(r[0]), "=r"(r[1]), "=r"(r[2]), "=r"(r[3]) : "r"(addr));
}
__device__ __forceinline__ void mma16816(float* d, const uint32_t* a, const uint32_t* b) {
    asm("mma.sync.aligned.m16n8k16.row.col.f32.bf16.bf16.f32 "
        "{%0,%1,%2,%3}, {%4,%5,%6,%7}, {%8,%9}, {%0,%1,%2,%3};"
        : "+f"(d[0]), "+f"(d[1]), "+f"(d[2]), "+f"(d[3])
        : "r"(a[0]), "r"(a[1]), "r"(a[2]), "r"(a[3]), "r"(b[0]), "r"(b[1]));
}
__device__ __forceinline__ void cp16(uint32_t dst, const void* src) {
    asm volatile("cp.async.cg.shared.global [%0], [%1], 16;"
                 :: "r"(dst), "l"(src) : "memory");
}
__device__ __forceinline__ uint32_t pack_bf(float e, float o) {
    uint32_t r;
    asm("cvt.rn.bf16x2.f32 %0, %1, %2;" : "=r"(r) : "f"(o), "f"(e));
    return r;
}

// =====================================================================
// Kernel 0: weight bf16 hi/lo split -> [h][t][c][oc]
// =====================================================================
__global__ void wsplit_kernel(const float* __restrict__ cw)
{
    int idx = blockIdx.x*256 + threadIdx.x;
    if (idx >= HEADS*9*CIN*CPER) return;
    int oc  = idx & 63;
    int c   = (idx >> 6) & 255;
    int ht  = idx >> 14;
    int t   = ht % 9;
    int h   = ht / 9;
    float w = cw[(((size_t)(h*CPER + oc))*CIN + c)*9 + t];
    __nv_bfloat16 hi = __float2bfloat16(w);
    float hf = __bfloat162float(hi);
    __nv_bfloat16 lo = __float2bfloat16(w - hf);
    g_wh[idx] = __bfloat16_as_ushort(hi);
    g_wl[idx] = __bfloat16_as_ushort(lo);
}

// =====================================================================
// Kernel 1: BN+ReLU fused global average pool
// =====================================================================
__global__ void bn_pool_kernel(const float* __restrict__ x,
                               const float* __restrict__ gmm,
                               const float* __restrict__ bet,
                               const float* __restrict__ mea,
                               const float* __restrict__ var)
{
    int bc = blockIdx.x;
    int c  = bc & (CIN-1);
    float a  = gmm[c] * rsqrtf(var[c] + BN_EPS);
    float sh = bet[c] - mea[c] * a;
    const float4* xp = (const float4*)(x + (size_t)bc * NPIX);
    float s = 0.f;
    for (int i = threadIdx.x; i < NPIX/4; i += 256) {
        float4 v = xp[i];
        s += fmaxf(fmaf(v.x, a, sh), 0.f) + fmaxf(fmaf(v.y, a, sh), 0.f)
           + fmaxf(fmaf(v.z, a, sh), 0.f) + fmaxf(fmaf(v.w, a, sh), 0.f);
    }
    #pragma unroll
    for (int o = 16; o; o >>= 1) s += __shfl_xor_sync(0xffffffffu, s, o);
    __shared__ float r8[8];
    if ((threadIdx.x & 31) == 0) r8[threadIdx.x >> 5] = s;
    __syncthreads();
    if (threadIdx.x < 8) {
        float v = r8[threadIdx.x];
        #pragma unroll
        for (int o = 4; o; o >>= 1) v += __shfl_xor_sync(0xffu, v, o);
        if (threadIdx.x == 0) g_xavg[bc] = v * (1.f / (float)NPIX);
    }
}

// =====================================================================
// Kernel 2: SE gate + exact top-k threshold + compaction + lasso
// =====================================================================
__global__ void se_kernel(const float* __restrict__ fc1,
                          const float* __restrict__ fc2,
                          const float* __restrict__ fcb,
                          const int*   inact_p,
                          float*       lasso_out)
{
    __shared__ float sav[256];
    __shared__ float sy[16];
    __shared__ float ssort[256];
    __shared__ int   wcnt[8];
    __shared__ int   woff[9];

    int hb = blockIdx.x;
    int h  = hb >> 4, b = hb & 15;
    int tid = threadIdx.x;

    sav[tid] = g_xavg[b*CIN + tid];
    __syncthreads();

    if (tid < 16) {
        const float* w = fc1 + (h*16 + tid)*256;
        float s = 0.f;
        #pragma unroll 8
        for (int c = 0; c < 256; ++c) s = fmaf(w[c], sav[c], s);
        sy[tid] = fmaxf(s, 0.f);
    }
    __syncthreads();

    float m;
    {
        const float* w = fc2 + ((size_t)(h*256 + tid)) * 16;
        float s = fcb[h*256 + tid];
        #pragma unroll
        for (int r = 0; r < 16; ++r) s = fmaf(w[r], sy[r], s);
        m = fmaxf(s, 0.f);
    }
    ssort[tid] = m;
    __syncthreads();

    sav[tid] = m;
    __syncthreads();
    for (int st = 128; st > 0; st >>= 1) {
        if (tid < st) sav[tid] += sav[tid + st];
        __syncthreads();
    }
    if (tid == 0) {
        g_lasso_part[hb] = sav[0];
        __threadfence();
        int ticket = atomicAdd(&g_lasso_cnt, 1);
        if (ticket == HB_N - 1) {
            if (lasso_out) {
                volatile float* vp = g_lasso_part;
                float s = 0.f;
                for (int i = 0; i < HB_N; ++i) s += vp[i];
                *lasso_out = s * (1.f / (float)(BATCH*CIN));
            }
            g_lasso_cnt = 0;
        }
    }
    __syncthreads();

    for (int k = 2; k <= 256; k <<= 1) {
        for (int j = k >> 1; j > 0; j >>= 1) {
            int ixj = tid ^ j;
            if (ixj > tid) {
                float va = ssort[tid], vb = ssort[ixj];
                bool up = ((tid & k) == 0);
                if ((va > vb) == up) { ssort[tid] = vb; ssort[ixj] = va; }
            }
            __syncthreads();
        }
    }

    int inact = 192;
    if (inact_p) {
        int iv = *inact_p;
        if (iv < 0 || iv > 256) {
            float f = __int_as_float(iv);
            iv = (f >= 0.f && f <= 256.f) ? (int)(f + 0.5f) : 192;
        }
        inact = iv;
    }
    float thresh = (inact > 0) ? ssort[min(inact,256) - 1] : -1e30f;

    bool keep = (m > thresh);
    unsigned ball = __ballot_sync(0xffffffffu, keep);
    int wid = tid >> 5, lane = tid & 31;
    if (lane == 0) wcnt[wid] = __popc(ball);
    __syncthreads();
    if (tid == 0) {
        int o = 0;
        #pragma unroll
        for (int w = 0; w < 8; ++w) { woff[w] = o; o += wcnt[w]; }
        woff[8] = o;
        g_act_cnt[hb] = o;
    }
    __syncthreads();
    int total = woff[8];
    int padded = (total + 15) & ~15;
    if (tid >= total && tid < padded) {
        g_act_idx[hb*256 + tid] = 0;
        g_act_val[hb*256 + tid] = 0.f;
    }
    if (keep) {
        int slot = woff[wid] + __popc(ball & ((1u << lane) - 1));
        g_act_idx[hb*256 + slot] = tid;
        g_act_val[hb*256 + slot] = m;
    }
}

// =====================================================================
// conv staging helpers
// =====================================================================
struct ConstView { int* sch; float* sca; float* scb; float* scm; };

__device__ __forceinline__ void stage_consts(
    ConstView cv, int slot, int ckbase, int cnt, int hb, int tid,
    const float* gmm, const float* bet, const float* mea, const float* var)
{
    if (tid < 16) {
        int pos = ckbase + tid;
        int ch = 0; float mv = 0.f;
        if (pos < cnt) { ch = g_act_idx[hb*256 + pos]; mv = g_act_val[hb*256 + pos]; }
        float a  = gmm[ch] * rsqrtf(var[ch] + BN_EPS);
        cv.sch[slot*16 + tid] = ch;
        cv.sca[slot*16 + tid] = a;
        cv.scb[slot*16 + tid] = bet[ch] - mea[ch] * a;
        cv.scm[slot*16 + tid] = mv;
    }
}

// combined-row plane staging (prologue): row = [16 hi][16 lo][pad]
__device__ __forceinline__ void stage_plane(
    ConstView cv, int cs, const float* __restrict__ xb, bool xin, size_t xoff,
    char* pDst, int tid)
{
    if (tid >= PLROWS) return;
    char* rowp = pDst + tid*PITCH_PB;
    if (!xin) {
        #pragma unroll
        for (int j = 0; j < 8; ++j) {
            *(uint32_t*)(rowp + j*4)      = 0u;
            *(uint32_t*)(rowp + 32 + j*4) = 0u;
        }
        return;
    }
    #pragma unroll
    for (int g = 0; g < 2; ++g) {
        float xv[8];
        #pragma unroll
        for (int j = 0; j < 8; ++j) {
            int ic = cs + g*8 + j;
            xv[j] = xb[(size_t)cv.sch[ic]*NPIX + xoff];
        }
        #pragma unroll
        for (int j = 0; j < 8; j += 2) {
            int ic = cs + g*8 + j;
            float v0 = fmaxf(fmaf(xv[j],   cv.sca[ic],   cv.scb[ic]),   0.f) * cv.scm[ic];
            float v1 = fmaxf(fmaf(xv[j+1], cv.sca[ic+1], cv.scb[ic+1]), 0.f) * cv.scm[ic+1];
            uint32_t hp = pack_bf(v0, v1);
            float h0 = __uint_as_float(hp << 16);
            float h1 = __uint_as_float(hp & 0xffff0000u);
            uint32_t lp = pack_bf(v0 - h0, v1 - h1);
            int eo = g*16 + j*2;
            *(uint32_t*)(rowp + eo)      = hp;
            *(uint32_t*)(rowp + 32 + eo) = lp;
        }
    }
}

// cvt+STS from prefetched registers into combined-row plane buffer
__device__ __forceinline__ void store_plane_regs(
    ConstView cv, int cs, const float* pf, bool xin, char* pDst, int tid)
{
    if (tid >= PLROWS) return;
    char* rowp = pDst + tid*PITCH_PB;
    if (!xin) {
        #pragma unroll
        for (int j = 0; j < 8; ++j) {
            *(uint32_t*)(rowp + j*4)      = 0u;
            *(uint32_t*)(rowp + 32 + j*4) = 0u;
        }
        return;
    }
    #pragma unroll
    for (int j = 0; j < 16; j += 2) {
        int ic = cs + j;
        float v0 = fmaxf(fmaf(pf[j],   cv.sca[ic],   cv.scb[ic]),   0.f) * cv.scm[ic];
        float v1 = fmaxf(fmaf(pf[j+1], cv.sca[ic+1], cv.scb[ic+1]), 0.f) * cv.scm[ic+1];
        uint32_t hp = pack_bf(v0, v1);
        float h0 = __uint_as_float(hp << 16);
        float h1 = __uint_as_float(hp & 0xffff0000u);
        uint32_t lp = pack_bf(v0 - h0, v1 - h1);
        *(uint32_t*)(rowp + j*2)      = hp;
        *(uint32_t*)(rowp + 32 + j*2) = lp;
    }
}

// weights -> 128B-pitch XOR-swizzled tiles
__device__ __forceinline__ void issue_weights(
    ConstView cv, int slot, uint32_t wdst,
    const uint16_t* whBase, const uint16_t* wlBase, int tid)
{
    #pragma unroll
    for (int i = 0; i < 9; ++i) {
        int idx = tid + i*256;                 // 0..2303
        int arr = idx >= 1152;
        int r2  = idx - arr*1152;
        int row = r2 >> 3;                     // t*16+ic (0..143)
        int seg = r2 & 7;
        int ic  = row & 15, t = row >> 4;
        const uint16_t* src = (arr ? wlBase : whBase)
                            + (((t*CIN + cv.sch[slot*16 + ic]) << 6) + seg*8);
        cp16(wdst + (uint32_t)(arr*WTILE_B + row*128 + ((seg<<4) ^ ((row&7)<<4))), src);
    }
    asm volatile("cp.async.commit_group;" ::: "memory");
}

// one conv tap: ldsm + 12 mma  (mi=1 fragment is +16 rows = +1280 B)
#define TAP_BODY(t)                                                          \
    {                                                                        \
        int ky = (t) / 3, kx = (t) - ky*3;                                   \
        int sb = ((ky - 1)*PGRID + (kx - 1)) * PITCH_PB;                     \
        uint32_t ah[2][4], al[2][4];                                         \
        ldsm4((uint32_t)(aB + sb),            ah[0]);                        \
        ldsm4((uint32_t)(aB + sb + 1280),     ah[1]);                        \
        ldsm4((uint32_t)(aB + sb + 32),       al[0]);                        \
        ldsm4((uint32_t)(aB + sb + 1312),     al[1]);                        \
        uint32_t bh[4][2], bl[4][2];                                         \
        uint32_t wb = bB + (uint32_t)((t)*2048);                             \
        ldsm4t(wb + swB0,            &bh[0][0]);                             \
        ldsm4t(wb + swB1,            &bh[2][0]);                             \
        ldsm4t(wb + WTILE_B + swB0,  &bl[0][0]);                             \
        ldsm4t(wb + WTILE_B + swB1,  &bl[2][0]);                             \
        _Pragma("unroll")                                                    \
        for (int mi = 0; mi < 2; ++mi)                                       \
            _Pragma("unroll")                                                \
            for (int ni = 0; ni < 4; ++ni) {                                 \
                mma16816(d[mi][ni], ah[mi], bh[ni]);                         \
                mma16816(d[mi][ni], ah[mi], bl[ni]);                         \
                mma16816(d[mi][ni], al[mi], bh[ni]);                         \
            }                                                                \
    }

// =====================================================================
// Kernel 3: sparse grouped conv; single-barrier chunk pipeline,
//  double-buffered plane + weights, register-prefetched plane LDGs.
// =====================================================================
__global__ __launch_bounds__(256, 2)
void conv_mma_kernel(const float* __restrict__ x,
                     const float* __restrict__ gmm,
                     const float* __restrict__ bet,
                     const float* __restrict__ mea,
                     const float* __restrict__ var,
                     float* __restrict__ out)
{
    extern __shared__ __align__(16) char dsm[];
    ConstView cv;
    cv.sch = (int*)(dsm + OFF_C);
    cv.sca = (float*)(dsm + OFF_C + 128);
    cv.scb = (float*)(dsm + OFF_C + 256);
    cv.scm = (float*)(dsm + OFF_C + 384);

    int tid  = threadIdx.x;
    int wid  = tid >> 5, lane = tid & 31;
    int wm   = wid >> 1, wn = wid & 1;
    int grp  = lane >> 2, qd = lane & 3;

    int hb = blockIdx.y;
    int h  = hb >> 4, b = hb & 15;
    int q0 = blockIdx.x * 128;

    // staging pixel mapping (row p = tid)
    int pg = q0 - 59 + tid;
    bool pin = (tid < PLROWS) && (pg >= 0) && (pg < PTOT);
    int rp = pg / PGRID, cp = pg - rp*PGRID;
    int rr = rp - 1, cc = cp - 1;
    bool xin = pin && ((unsigned)rr < (unsigned)HH) && ((unsigned)cc < (unsigned)WW);
    size_t xoff = (size_t)rr*WW + cc;
    const float* xb = x + (size_t)b*CIN*NPIX;

    int cnt = g_act_cnt[hb];
    int nchunks = (cnt + 15) >> 4;

    float d[2][4][4];
    #pragma unroll
    for (int mi = 0; mi < 2; ++mi)
        #pragma unroll
        for (int ni = 0; ni < 4; ++ni)
            #pragma unroll
            for (int k = 0; k < 4; ++k) d[mi][ni][k] = 0.f;

    uint32_t smb = smem_u32(dsm);
    uint32_t aOff = (uint32_t)((59 + wm*32 + (lane & 15))*PITCH_PB + ((lane >> 4) << 4));
    uint32_t bc0  = (uint32_t)(wn*64 + ((lane >> 4) << 4));
    uint32_t swB0 = (uint32_t)((lane & 15)*128) + (bc0 ^ (uint32_t)((lane & 7) << 4));
    uint32_t swB1 = swB0 ^ 32u;

    const uint16_t* whBase = g_wh + ((size_t)h*9*CIN << 6);
    const uint16_t* wlBase = g_wl + ((size_t)h*9*CIN << 6);

    // ---- prologue
    stage_consts(cv, 0, 0, cnt, hb, tid, gmm, bet, mea, var);
    __syncthreads();
    issue_weights(cv, 0, smb + OFF_W0H, whBase, wlBase, tid);
    stage_plane(cv, 0, xb, xin, xoff, dsm + OFF_P0, tid);
    if (nchunks > 1)
        stage_consts(cv, 1, 16, cnt, hb, tid, gmm, bet, mea, var);

    #pragma unroll 1
    for (int ck = 0; ck < nchunks; ++ck) {
        int buf = ck & 1;

        asm volatile("cp.async.wait_group 0;" ::: "memory");
        __syncthreads();   // B1: weights ck + plane ck + consts visible; prior readers done

        // weights for ck+1 into the other buffer (safe: ck-1 readers passed B1)
        if (ck + 1 < nchunks)
            issue_weights(cv, buf^1, smb + (buf ? OFF_W0H : OFF_W1H), whBase, wlBase, tid);
        // consts for ck+2 into slot buf (ck's consts no longer needed)
        if (ck + 2 < nchunks)
            stage_consts(cv, buf, (ck+2)*16, cnt, hb, tid, gmm, bet, mea, var);

        bool dopf = (ck + 1 < nchunks) && xin;
        int csN = (buf^1)*16;
        float pf[16];

        uint32_t aB = smb + (buf ? OFF_P1 : OFF_P0) + aOff;
        uint32_t bB = smb + (buf ? OFF_W1H : OFF_W0H);

        TAP_BODY(0) TAP_BODY(1) TAP_BODY(2)
        if (dopf) {
            #pragma unroll
            for (int j = 0; j < 8; ++j)
                pf[j] = xb[(size_t)cv.sch[csN + j]*NPIX + xoff];
        }
        TAP_BODY(3) TAP_BODY(4) TAP_BODY(5)
        if (dopf) {
            #pragma unroll
            for (int j = 0; j < 8; ++j)
                pf[8+j] = xb[(size_t)cv.sch[csN + 8 + j]*NPIX + xoff];
        }
        TAP_BODY(6) TAP_BODY(7) TAP_BODY(8)

        // plane for ck+1 into the other buffer — next iter's B1 publishes it.
        if (ck + 1 < nchunks)
            store_plane_regs(cv, csN, pf, xin, dsm + (buf ? OFF_P0 : OFF_P1), tid);
    }

    // ---- epilogue
    #pragma unroll
    for (int mi = 0; mi < 2; ++mi) {
        #pragma unroll
        for (int dr = 0; dr < 2; ++dr) {
            int row = wm*32 + mi*16 + dr*8 + grp;
            int q   = q0 + row;
            int rp2 = q / PGRID, cp2 = q - rp2*PGRID;
            bool v = (rp2 >= 1) && (rp2 <= HH) && (cp2 >= 1) && (cp2 <= WW);
            if (v) {
                size_t ob = ((size_t)b*(HEADS*CPER) + h)*NPIX
                          + (size_t)(rp2-1)*WW + (cp2-1);
                #pragma unroll
                for (int ni = 0; ni < 4; ++ni) {
                    int oc = wn*32 + ni*8 + qd*2;
                    out[ob + (size_t)(oc*HEADS)*NPIX]     = d[mi][ni][dr*2 + 0];
                    out[ob + (size_t)((oc+1)*HEADS)*NPIX] = d[mi][ni][dr*2 + 1];
                }
            }
        }
    }
}

// =====================================================================
extern "C" void kernel_launch(void* const* d_in, const int* in_sizes, int n_in,
                              void* d_out, int out_size)
{
    const float* x    = (const float*)d_in[0];
    const float* gmm  = (const float*)d_in[1];
    const float* bet  = (const float*)d_in[2];
    const float* mea  = (const float*)d_in[3];
    const float* var  = (const float*)d_in[4];
    const float* fc1  = (const float*)d_in[5];
    const float* fc2  = (const float*)d_in[6];
    const float* fcb  = (const float*)d_in[7];
    const float* cw   = (const float*)d_in[8];
    const int*   inact = (n_in > 9) ? (const int*)d_in[9] : nullptr;
    float* out = (float*)d_out;
    float* lasso_out = (out_size > NOUT) ? (out + NOUT) : nullptr;

    bn_pool_kernel<<<BATCH*CIN, 256>>>(x, gmm, bet, mea, var);
    wsplit_kernel<<<(HEADS*9*CIN*CPER + 255)/256, 256>>>(cw);
    se_kernel<<<HB_N, 256>>>(fc1, fc2, fcb, inact, lasso_out);

    cudaFuncSetAttribute(conv_mma_kernel, cudaFuncAttributeMaxDynamicSharedMemorySize,
                         SMEM_BYTES);
    dim3 grid(NTILES, HB_N);
    conv_mma_kernel<<<grid, 256, SMEM_BYTES>>>(x, gmm, bet, mea, var, out);
}

// round 15
// speedup vs baseline: 1.3963x; 1.2064x over previous
#include <cuda_runtime.h>
#include <cuda_bf16.h>
#include <cuda_fp16.h>
#include <math.h>
#include <stdint.h>

#define BATCH   16
#define CIN     256
#define HH      56
#define WW      56
#define HEADS   4
#define CPER    64
#define HB_N    64
#define NPIX    3136
#define NOUT    (BATCH*HEADS*CPER*NPIX)
#define BN_EPS  1e-5f

#define PGRID   58
#define PTOT    (PGRID*PGRID)
#define NTILES  26
#define PLROWS  246
#define PITCH_PB 48              // bytes per plane row: [16 ic fp16 | 16 pad]

// dynamic smem byte offsets
#define WTILE_B  18432           // 144 rows * 128 B (XOR-swizzled)
#define OFF_W0H  0
#define OFF_W0L  18432
#define OFF_W1H  36864
#define OFF_W1L  55296
#define OFF_P0   73728           // 246*48 = 11808
#define OFF_P1   85536
#define OFF_C    97344           // sch[2][16], sca[2][16], scb[2][16], scm[2][16]
#define SMEM_BYTES 97856

__device__ float g_xavg[BATCH*CIN];
__device__ int   g_act_idx[HB_N*256];
__device__ float g_act_val[HB_N*256];
__device__ int   g_act_cnt[HB_N];
__device__ float g_lasso_part[HB_N];
__device__ int   g_lasso_cnt = 0;
__device__ __align__(16) uint16_t g_wh[HEADS*9*CIN*CPER];  // fp16 hi, [h][t][c][oc]
__device__ __align__(16) uint16_t g_wl[HEADS*9*CIN*CPER];  // fp16 lo

// ------------------------- helpers -------------------------
__device__ __forceinline__ uint32_t smem_u32(const void* p) {
    uint32_t a;
    asm("{ .reg .u64 t; cvta.to.shared.u64 t, %1; cvt.u32.u64 %0, t; }" : "=r"(a) : "l"(p));
    return a;
}
__device__ __forceinline__ void ldsm4(uint32_t addr, uint32_t* r) {
    asm("ldmatrix.sync.aligned.m8n8.x4.shared.b16 {%0,%1,%2,%3}, [%4];"
        : "=r"(r[0]), "=r"(r[1]), "=r"(r[2]), "=r"(r[3]) : "r"(addr));
}
__device__ __forceinline__ void ldsm4t(uint32_t addr, uint32_t* r) {
    asm("ldmatrix.sync.aligned.m8n8.x4.trans.shared.b16 {%0,%1,%2,%3}, [%4];"
        : "=r"(r[0]), "=r"(r[1]), "=r"(r[2]), "=r"(r[3]) : "r"(addr));
}
__device__ __forceinline__ void mma16816(float* d, const uint32_t* a, const uint32_t* b) {
    asm("mma.sync.aligned.m16n8k16.row.col.f32.f16.f16.f32 "
        "{%0,%1,%2,%3}, {%4,%5,%6,%7}, {%8,%9}, {%0,%1,%2,%3};"
        : "+f"(d[0]), "+f"(d[1]), "+f"(d[2]), "+f"(d[3])
        : "r"(a[0]), "r"(a[1]), "r"(a[2]), "r"(a[3]), "r"(b[0]), "r"(b[1]));
}
__device__ __forceinline__ void cp16(uint32_t dst, const void* src) {
    asm volatile("cp.async.cg.shared.global [%0], [%1], 16;"
                 :: "r"(dst), "l"(src) : "memory");
}
__device__ __forceinline__ uint32_t pack_f16(float e, float o) {
    // low half = fp16(e), high half = fp16(o); RN
    uint32_t r;
    asm("cvt.rn.f16x2.f32 %0, %1, %2;" : "=r"(r) : "f"(o), "f"(e));
    return r;
}

// =====================================================================
// Kernel 0: weight fp16 hi/lo split -> [h][t][c][oc]
// =====================================================================
__global__ void wsplit_kernel(const float* __restrict__ cw)
{
    int idx = blockIdx.x*256 + threadIdx.x;
    if (idx >= HEADS*9*CIN*CPER) return;
    int oc  = idx & 63;
    int c   = (idx >> 6) & 255;
    int ht  = idx >> 14;
    int t   = ht % 9;
    int h   = ht / 9;
    float w = cw[(((size_t)(h*CPER + oc))*CIN + c)*9 + t];
    __half hi = __float2half(w);
    float hf = __half2float(hi);
    __half lo = __float2half(w - hf);
    g_wh[idx] = __half_as_ushort(hi);
    g_wl[idx] = __half_as_ushort(lo);
}

// =====================================================================
// Kernel 1: BN+ReLU fused global average pool
// =====================================================================
__global__ void bn_pool_kernel(const float* __restrict__ x,
                               const float* __restrict__ gmm,
                               const float* __restrict__ bet,
                               const float* __restrict__ mea,
                               const float* __restrict__ var)
{
    int bc = blockIdx.x;
    int c  = bc & (CIN-1);
    float a  = gmm[c] * rsqrtf(var[c] + BN_EPS);
    float sh = bet[c] - mea[c] * a;
    const float4* xp = (const float4*)(x + (size_t)bc * NPIX);
    float s = 0.f;
    for (int i = threadIdx.x; i < NPIX/4; i += 256) {
        float4 v = xp[i];
        s += fmaxf(fmaf(v.x, a, sh), 0.f) + fmaxf(fmaf(v.y, a, sh), 0.f)
           + fmaxf(fmaf(v.z, a, sh), 0.f) + fmaxf(fmaf(v.w, a, sh), 0.f);
    }
    #pragma unroll
    for (int o = 16; o; o >>= 1) s += __shfl_xor_sync(0xffffffffu, s, o);
    __shared__ float r8[8];
    if ((threadIdx.x & 31) == 0) r8[threadIdx.x >> 5] = s;
    __syncthreads();
    if (threadIdx.x < 8) {
        float v = r8[threadIdx.x];
        #pragma unroll
        for (int o = 4; o; o >>= 1) v += __shfl_xor_sync(0xffu, v, o);
        if (threadIdx.x == 0) g_xavg[bc] = v * (1.f / (float)NPIX);
    }
}

// =====================================================================
// Kernel 2: SE gate + exact top-k threshold + compaction + lasso
// =====================================================================
__global__ void se_kernel(const float* __restrict__ fc1,
                          const float* __restrict__ fc2,
                          const float* __restrict__ fcb,
                          const int*   inact_p,
                          float*       lasso_out)
{
    __shared__ float sav[256];
    __shared__ float sy[16];
    __shared__ float ssort[256];
    __shared__ int   wcnt[8];
    __shared__ int   woff[9];

    int hb = blockIdx.x;
    int h  = hb >> 4, b = hb & 15;
    int tid = threadIdx.x;

    sav[tid] = g_xavg[b*CIN + tid];
    __syncthreads();

    if (tid < 16) {
        const float* w = fc1 + (h*16 + tid)*256;
        float s = 0.f;
        #pragma unroll 8
        for (int c = 0; c < 256; ++c) s = fmaf(w[c], sav[c], s);
        sy[tid] = fmaxf(s, 0.f);
    }
    __syncthreads();

    float m;
    {
        const float* w = fc2 + ((size_t)(h*256 + tid)) * 16;
        float s = fcb[h*256 + tid];
        #pragma unroll
        for (int r = 0; r < 16; ++r) s = fmaf(w[r], sy[r], s);
        m = fmaxf(s, 0.f);
    }
    ssort[tid] = m;
    __syncthreads();

    sav[tid] = m;
    __syncthreads();
    for (int st = 128; st > 0; st >>= 1) {
        if (tid < st) sav[tid] += sav[tid + st];
        __syncthreads();
    }
    if (tid == 0) {
        g_lasso_part[hb] = sav[0];
        __threadfence();
        int ticket = atomicAdd(&g_lasso_cnt, 1);
        if (ticket == HB_N - 1) {
            if (lasso_out) {
                volatile float* vp = g_lasso_part;
                float s = 0.f;
                for (int i = 0; i < HB_N; ++i) s += vp[i];
                *lasso_out = s * (1.f / (float)(BATCH*CIN));
            }
            g_lasso_cnt = 0;
        }
    }
    __syncthreads();

    for (int k = 2; k <= 256; k <<= 1) {
        for (int j = k >> 1; j > 0; j >>= 1) {
            int ixj = tid ^ j;
            if (ixj > tid) {
                float va = ssort[tid], vb = ssort[ixj];
                bool up = ((tid & k) == 0);
                if ((va > vb) == up) { ssort[tid] = vb; ssort[ixj] = va; }
            }
            __syncthreads();
        }
    }

    int inact = 192;
    if (inact_p) {
        int iv = *inact_p;
        if (iv < 0 || iv > 256) {
            float f = __int_as_float(iv);
            iv = (f >= 0.f && f <= 256.f) ? (int)(f + 0.5f) : 192;
        }
        inact = iv;
    }
    float thresh = (inact > 0) ? ssort[min(inact,256) - 1] : -1e30f;

    bool keep = (m > thresh);
    unsigned ball = __ballot_sync(0xffffffffu, keep);
    int wid = tid >> 5, lane = tid & 31;
    if (lane == 0) wcnt[wid] = __popc(ball);
    __syncthreads();
    if (tid == 0) {
        int o = 0;
        #pragma unroll
        for (int w = 0; w < 8; ++w) { woff[w] = o; o += wcnt[w]; }
        woff[8] = o;
        g_act_cnt[hb] = o;
    }
    __syncthreads();
    int total = woff[8];
    int padded = (total + 15) & ~15;
    if (tid >= total && tid < padded) {
        g_act_idx[hb*256 + tid] = 0;
        g_act_val[hb*256 + tid] = 0.f;
    }
    if (keep) {
        int slot = woff[wid] + __popc(ball & ((1u << lane) - 1));
        g_act_idx[hb*256 + slot] = tid;
        g_act_val[hb*256 + slot] = m;
    }
}

// =====================================================================
// conv staging helpers
// =====================================================================
struct ConstView { int* sch; float* sca; float* scb; float* scm; };

__device__ __forceinline__ void stage_consts(
    ConstView cv, int slot, int ckbase, int cnt, int hb, int tid,
    const float* gmm, const float* bet, const float* mea, const float* var)
{
    if (tid < 16) {
        int pos = ckbase + tid;
        int ch = 0; float mv = 0.f;
        if (pos < cnt) { ch = g_act_idx[hb*256 + pos]; mv = g_act_val[hb*256 + pos]; }
        float a  = gmm[ch] * rsqrtf(var[ch] + BN_EPS);
        cv.sch[slot*16 + tid] = ch;
        cv.sca[slot*16 + tid] = a;
        cv.scb[slot*16 + tid] = bet[ch] - mea[ch] * a;
        cv.scm[slot*16 + tid] = mv;
    }
}

// plane staging (prologue): row = [16 ic fp16]
__device__ __forceinline__ void stage_plane(
    ConstView cv, int cs, const float* __restrict__ xb, bool xin, size_t xoff,
    char* pDst, int tid)
{
    if (tid >= PLROWS) return;
    char* rowp = pDst + tid*PITCH_PB;
    if (!xin) {
        #pragma unroll
        for (int j = 0; j < 8; ++j)
            *(uint32_t*)(rowp + j*4) = 0u;
        return;
    }
    #pragma unroll
    for (int g = 0; g < 2; ++g) {
        float xv[8];
        #pragma unroll
        for (int j = 0; j < 8; ++j) {
            int ic = cs + g*8 + j;
            xv[j] = xb[(size_t)cv.sch[ic]*NPIX + xoff];
        }
        #pragma unroll
        for (int j = 0; j < 8; j += 2) {
            int ic = cs + g*8 + j;
            float v0 = fmaxf(fmaf(xv[j],   cv.sca[ic],   cv.scb[ic]),   0.f) * cv.scm[ic];
            float v1 = fmaxf(fmaf(xv[j+1], cv.sca[ic+1], cv.scb[ic+1]), 0.f) * cv.scm[ic+1];
            *(uint32_t*)(rowp + (g*8 + j)*2) = pack_f16(v0, v1);
        }
    }
}

// cvt+STS from prefetched registers
__device__ __forceinline__ void store_plane_regs(
    ConstView cv, int cs, const float* pf, bool xin, char* pDst, int tid)
{
    if (tid >= PLROWS) return;
    char* rowp = pDst + tid*PITCH_PB;
    if (!xin) {
        #pragma unroll
        for (int j = 0; j < 8; ++j)
            *(uint32_t*)(rowp + j*4) = 0u;
        return;
    }
    #pragma unroll
    for (int j = 0; j < 16; j += 2) {
        int ic = cs + j;
        float v0 = fmaxf(fmaf(pf[j],   cv.sca[ic],   cv.scb[ic]),   0.f) * cv.scm[ic];
        float v1 = fmaxf(fmaf(pf[j+1], cv.sca[ic+1], cv.scb[ic+1]), 0.f) * cv.scm[ic+1];
        *(uint32_t*)(rowp + j*2) = pack_f16(v0, v1);
    }
}

// weights -> 128B-pitch XOR-swizzled tiles (hi + lo arrays)
__device__ __forceinline__ void issue_weights(
    ConstView cv, int slot, uint32_t wdst,
    const uint16_t* whBase, const uint16_t* wlBase, int tid)
{
    #pragma unroll
    for (int i = 0; i < 9; ++i) {
        int idx = tid + i*256;                 // 0..2303
        int arr = idx >= 1152;
        int r2  = idx - arr*1152;
        int row = r2 >> 3;                     // t*16+ic (0..143)
        int seg = r2 & 7;
        int ic  = row & 15, t = row >> 4;
        const uint16_t* src = (arr ? wlBase : whBase)
                            + (((t*CIN + cv.sch[slot*16 + ic]) << 6) + seg*8);
        cp16(wdst + (uint32_t)(arr*WTILE_B + row*128 + ((seg<<4) ^ ((row&7)<<4))), src);
    }
    asm volatile("cp.async.commit_group;" ::: "memory");
}

// one conv tap: 6 ldsm + 16 mma (fp16 2-pass: ah*bh + ah*bl)
#define TAP_BODY(t)                                                          \
    {                                                                        \
        int ky = (t) / 3, kx = (t) - ky*3;                                   \
        int sb = ((ky - 1)*PGRID + (kx - 1)) * PITCH_PB;                     \
        uint32_t ah[2][4];                                                   \
        ldsm4((uint32_t)(aB + sb),        ah[0]);                            \
        ldsm4((uint32_t)(aB + sb + 768),  ah[1]);                            \
        uint32_t bh[4][2], bl[4][2];                                         \
        uint32_t wb = bB + (uint32_t)((t)*2048);                             \
        ldsm4t(wb + swB0,            &bh[0][0]);                             \
        ldsm4t(wb + swB1,            &bh[2][0]);                             \
        ldsm4t(wb + WTILE_B + swB0,  &bl[0][0]);                             \
        ldsm4t(wb + WTILE_B + swB1,  &bl[2][0]);                             \
        _Pragma("unroll")                                                    \
        for (int mi = 0; mi < 2; ++mi)                                       \
            _Pragma("unroll")                                                \
            for (int ni = 0; ni < 4; ++ni) {                                 \
                mma16816(d[mi][ni], ah[mi], bh[ni]);                         \
                mma16816(d[mi][ni], ah[mi], bl[ni]);                         \
            }                                                                \
    }

// =====================================================================
// Kernel 3: sparse grouped conv; single-barrier chunk pipeline,
//  fp16 2-pass mma, double-buffered plane + weights, reg-prefetch.
// =====================================================================
__global__ __launch_bounds__(256, 2)
void conv_mma_kernel(const float* __restrict__ x,
                     const float* __restrict__ gmm,
                     const float* __restrict__ bet,
                     const float* __restrict__ mea,
                     const float* __restrict__ var,
                     float* __restrict__ out)
{
    extern __shared__ __align__(16) char dsm[];
    ConstView cv;
    cv.sch = (int*)(dsm + OFF_C);
    cv.sca = (float*)(dsm + OFF_C + 128);
    cv.scb = (float*)(dsm + OFF_C + 256);
    cv.scm = (float*)(dsm + OFF_C + 384);

    int tid  = threadIdx.x;
    int wid  = tid >> 5, lane = tid & 31;
    int wm   = wid >> 1, wn = wid & 1;
    int grp  = lane >> 2, qd = lane & 3;

    int hb = blockIdx.y;
    int h  = hb >> 4, b = hb & 15;
    int q0 = blockIdx.x * 128;

    // staging pixel mapping (row p = tid)
    int pg = q0 - 59 + tid;
    bool pin = (tid < PLROWS) && (pg >= 0) && (pg < PTOT);
    int rp = pg / PGRID, cp = pg - rp*PGRID;
    int rr = rp - 1, cc = cp - 1;
    bool xin = pin && ((unsigned)rr < (unsigned)HH) && ((unsigned)cc < (unsigned)WW);
    size_t xoff = (size_t)rr*WW + cc;
    const float* xb = x + (size_t)b*CIN*NPIX;

    int cnt = g_act_cnt[hb];
    int nchunks = (cnt + 15) >> 4;

    float d[2][4][4];
    #pragma unroll
    for (int mi = 0; mi < 2; ++mi)
        #pragma unroll
        for (int ni = 0; ni < 4; ++ni)
            #pragma unroll
            for (int k = 0; k < 4; ++k) d[mi][ni][k] = 0.f;

    uint32_t smb = smem_u32(dsm);
    uint32_t aOff = (uint32_t)((59 + wm*32 + (lane & 15))*PITCH_PB + ((lane >> 4) << 4));
    uint32_t bc0  = (uint32_t)(wn*64 + ((lane >> 4) << 4));
    uint32_t swB0 = (uint32_t)((lane & 15)*128) + (bc0 ^ (uint32_t)((lane & 7) << 4));
    uint32_t swB1 = swB0 ^ 32u;

    const uint16_t* whBase = g_wh + ((size_t)h*9*CIN << 6);
    const uint16_t* wlBase = g_wl + ((size_t)h*9*CIN << 6);

    // ---- prologue
    stage_consts(cv, 0, 0, cnt, hb, tid, gmm, bet, mea, var);
    __syncthreads();
    issue_weights(cv, 0, smb + OFF_W0H, whBase, wlBase, tid);
    stage_plane(cv, 0, xb, xin, xoff, dsm + OFF_P0, tid);
    if (nchunks > 1)
        stage_consts(cv, 1, 16, cnt, hb, tid, gmm, bet, mea, var);

    #pragma unroll 1
    for (int ck = 0; ck < nchunks; ++ck) {
        int buf = ck & 1;

        asm volatile("cp.async.wait_group 0;" ::: "memory");
        __syncthreads();   // B1: weights ck + plane ck + consts visible; prior readers done

        if (ck + 1 < nchunks)
            issue_weights(cv, buf^1, smb + (buf ? OFF_W0H : OFF_W1H), whBase, wlBase, tid);
        if (ck + 2 < nchunks)
            stage_consts(cv, buf, (ck+2)*16, cnt, hb, tid, gmm, bet, mea, var);

        bool dopf = (ck + 1 < nchunks) && xin;
        int csN = (buf^1)*16;
        float pf[16];

        uint32_t aB = smb + (buf ? OFF_P1 : OFF_P0) + aOff;
        uint32_t bB = smb + (buf ? OFF_W1H : OFF_W0H);

        TAP_BODY(0) TAP_BODY(1) TAP_BODY(2)
        if (dopf) {
            #pragma unroll
            for (int j = 0; j < 8; ++j)
                pf[j] = xb[(size_t)cv.sch[csN + j]*NPIX + xoff];
        }
        TAP_BODY(3) TAP_BODY(4) TAP_BODY(5)
        if (dopf) {
            #pragma unroll
            for (int j = 0; j < 8; ++j)
                pf[8+j] = xb[(size_t)cv.sch[csN + 8 + j]*NPIX + xoff];
        }
        TAP_BODY(6) TAP_BODY(7) TAP_BODY(8)

        // plane for ck+1 into the other buffer — next iter's B1 publishes it.
        if (ck + 1 < nchunks)
            store_plane_regs(cv, csN, pf, xin, dsm + (buf ? OFF_P0 : OFF_P1), tid);
    }

    // ---- epilogue
    #pragma unroll
    for (int mi = 0; mi < 2; ++mi) {
        #pragma unroll
        for (int dr = 0; dr < 2; ++dr) {
            int row = wm*32 + mi*16 + dr*8 + grp;
            int q   = q0 + row;
            int rp2 = q / PGRID, cp2 = q - rp2*PGRID;
            bool v = (rp2 >= 1) && (rp2 <= HH) && (cp2 >= 1) && (cp2 <= WW);
            if (v) {
                size_t ob = ((size_t)b*(HEADS*CPER) + h)*NPIX
                          + (size_t)(rp2-1)*WW + (cp2-1);
                #pragma unroll
                for (int ni = 0; ni < 4; ++ni) {
                    int oc = wn*32 + ni*8 + qd*2;
                    out[ob + (size_t)(oc*HEADS)*NPIX]     = d[mi][ni][dr*2 + 0];
                    out[ob + (size_t)((oc+1)*HEADS)*NPIX] = d[mi][ni][dr*2 + 1];
                }
            }
        }
    }
}

// =====================================================================
extern "C" void kernel_launch(void* const* d_in, const int* in_sizes, int n_in,
                              void* d_out, int out_size)
{
    const float* x    = (const float*)d_in[0];
    const float* gmm  = (const float*)d_in[1];
    const float* bet  = (const float*)d_in[2];
    const float* mea  = (const float*)d_in[3];
    const float* var  = (const float*)d_in[4];
    const float* fc1  = (const float*)d_in[5];
    const float* fc2  = (const float*)d_in[6];
    const float* fcb  = (const float*)d_in[7];
    const float* cw   = (const float*)d_in[8];
    const int*   inact = (n_in > 9) ? (const int*)d_in[9] : nullptr;
    float* out = (float*)d_out;
    float* lasso_out = (out_size > NOUT) ? (out + NOUT) : nullptr;

    bn_pool_kernel<<<BATCH*CIN, 256>>>(x, gmm, bet, mea, var);
    wsplit_kernel<<<(HEADS*9*CIN*CPER + 255)/256, 256>>>(cw);
    se_kernel<<<HB_N, 256>>>(fc1, fc2, fcb, inact, lasso_out);

    cudaFuncSetAttribute(conv_mma_kernel, cudaFuncAttributeMaxDynamicSharedMemorySize,
                         SMEM_BYTES);
    dim3 grid(NTILES, HB_N);
    conv_mma_kernel<<<grid, 256, SMEM_BYTES>>>(x, gmm, bet, mea, var, out);
}

// round 16
// speedup vs baseline: 1.4248x; 1.0204x over previous
#include <cuda_runtime.h>
#include <cuda_bf16.h>
#include <cuda_fp16.h>
#include <math.h>
#include <stdint.h>

#define BATCH   16
#define CIN     256
#define HH      56
#define WW      56
#define HEADS   4
#define CPER    64
#define HB_N    64
#define NPIX    3136
#define NOUT    (BATCH*HEADS*CPER*NPIX)
#define BN_EPS  1e-5f

#define PGRID   58
#define PTOT    (PGRID*PGRID)
#define MTILE   256
#define NTILES  13
#define PLROWS  374              // 256 + 2*59 halo
#define PITCH_PB 48              // bytes per plane row: [16 ic fp16 | pad]

// dynamic smem byte offsets
#define WTILE_B  18432           // 144 rows * 128 B (XOR-swizzled)
#define OFF_W0H  0
#define OFF_W0L  18432
#define OFF_W1H  36864
#define OFF_W1L  55296
#define OFF_P0   73728           // 374*48 = 17952
#define OFF_P1   91680
#define OFF_C    109632          // sch[2][16], sca[2][16], scb[2][16], scm[2][16]
#define SMEM_BYTES 110144

__device__ float g_xavg[BATCH*CIN];
__device__ int   g_act_idx[HB_N*256];
__device__ float g_act_val[HB_N*256];
__device__ int   g_act_cnt[HB_N];
__device__ float g_lasso_part[HB_N];
__device__ int   g_lasso_cnt = 0;
__device__ __align__(16) uint16_t g_wh[HEADS*9*CIN*CPER];  // fp16 hi, [h][t][c][oc]
__device__ __align__(16) uint16_t g_wl[HEADS*9*CIN*CPER];  // fp16 lo

// ------------------------- helpers -------------------------
__device__ __forceinline__ uint32_t smem_u32(const void* p) {
    uint32_t a;
    asm("{ .reg .u64 t; cvta.to.shared.u64 t, %1; cvt.u32.u64 %0, t; }" : "=r"(a) : "l"(p));
    return a;
}
__device__ __forceinline__ void ldsm4(uint32_t addr, uint32_t* r) {
    asm("ldmatrix.sync.aligned.m8n8.x4.shared.b16 {%0,%1,%2,%3}, [%4];"
        : "=r"(r[0]), "=r"(r[1]), "=r"(r[2]), "=r"(r[3]) : "r"(addr));
}
__device__ __forceinline__ void ldsm4t(uint32_t addr, uint32_t* r) {
    asm("ldmatrix.sync.aligned.m8n8.x4.trans.shared.b16 {%0,%1,%2,%3}, [%4];"
        : "=r"(r[0]), "=r"(r[1]), "=r"(r[2]), "=r"(r[3]) : "r"(addr));
}
__device__ __forceinline__ void mma16816(float* d, const uint32_t* a, const uint32_t* b) {
    asm("mma.sync.aligned.m16n8k16.row.col.f32.f16.f16.f32 "
        "{%0,%1,%2,%3}, {%4,%5,%6,%7}, {%8,%9}, {%0,%1,%2,%3};"
        : "+f"(d[0]), "+f"(d[1]), "+f"(d[2]), "+f"(d[3])
        : "r"(a[0]), "r"(a[1]), "r"(a[2]), "r"(a[3]), "r"(b[0]), "r"(b[1]));
}
__device__ __forceinline__ void cp16(uint32_t dst, const void* src) {
    asm volatile("cp.async.cg.shared.global [%0], [%1], 16;"
                 :: "r"(dst), "l"(src) : "memory");
}
__device__ __forceinline__ uint32_t pack_f16(float e, float o) {
    uint32_t r;
    asm("cvt.rn.f16x2.f32 %0, %1, %2;" : "=r"(r) : "f"(o), "f"(e));
    return r;
}

// =====================================================================
// Kernel 0: weight fp16 hi/lo split -> [h][t][c][oc]
// =====================================================================
__global__ void wsplit_kernel(const float* __restrict__ cw)
{
    int idx = blockIdx.x*256 + threadIdx.x;
    if (idx >= HEADS*9*CIN*CPER) return;
    int oc  = idx & 63;
    int c   = (idx >> 6) & 255;
    int ht  = idx >> 14;
    int t   = ht % 9;
    int h   = ht / 9;
    float w = cw[(((size_t)(h*CPER + oc))*CIN + c)*9 + t];
    __half hi = __float2half(w);
    float hf = __half2float(hi);
    __half lo = __float2half(w - hf);
    g_wh[idx] = __half_as_ushort(hi);
    g_wl[idx] = __half_as_ushort(lo);
}

// =====================================================================
// Kernel 1: BN+ReLU fused global average pool
// =====================================================================
__global__ void bn_pool_kernel(const float* __restrict__ x,
                               const float* __restrict__ gmm,
                               const float* __restrict__ bet,
                               const float* __restrict__ mea,
                               const float* __restrict__ var)
{
    int bc = blockIdx.x;
    int c  = bc & (CIN-1);
    float a  = gmm[c] * rsqrtf(var[c] + BN_EPS);
    float sh = bet[c] - mea[c] * a;
    const float4* xp = (const float4*)(x + (size_t)bc * NPIX);
    float s = 0.f;
    for (int i = threadIdx.x; i < NPIX/4; i += 256) {
        float4 v = xp[i];
        s += fmaxf(fmaf(v.x, a, sh), 0.f) + fmaxf(fmaf(v.y, a, sh), 0.f)
           + fmaxf(fmaf(v.z, a, sh), 0.f) + fmaxf(fmaf(v.w, a, sh), 0.f);
    }
    #pragma unroll
    for (int o = 16; o; o >>= 1) s += __shfl_xor_sync(0xffffffffu, s, o);
    __shared__ float r8[8];
    if ((threadIdx.x & 31) == 0) r8[threadIdx.x >> 5] = s;
    __syncthreads();
    if (threadIdx.x < 8) {
        float v = r8[threadIdx.x];
        #pragma unroll
        for (int o = 4; o; o >>= 1) v += __shfl_xor_sync(0xffu, v, o);
        if (threadIdx.x == 0) g_xavg[bc] = v * (1.f / (float)NPIX);
    }
}

// =====================================================================
// Kernel 2: SE gate + exact top-k threshold + compaction + lasso
// =====================================================================
__global__ void se_kernel(const float* __restrict__ fc1,
                          const float* __restrict__ fc2,
                          const float* __restrict__ fcb,
                          const int*   inact_p,
                          float*       lasso_out)
{
    __shared__ float sav[256];
    __shared__ float sy[16];
    __shared__ float ssort[256];
    __shared__ int   wcnt[8];
    __shared__ int   woff[9];

    int hb = blockIdx.x;
    int h  = hb >> 4, b = hb & 15;
    int tid = threadIdx.x;

    sav[tid] = g_xavg[b*CIN + tid];
    __syncthreads();

    if (tid < 16) {
        const float* w = fc1 + (h*16 + tid)*256;
        float s = 0.f;
        #pragma unroll 8
        for (int c = 0; c < 256; ++c) s = fmaf(w[c], sav[c], s);
        sy[tid] = fmaxf(s, 0.f);
    }
    __syncthreads();

    float m;
    {
        const float* w = fc2 + ((size_t)(h*256 + tid)) * 16;
        float s = fcb[h*256 + tid];
        #pragma unroll
        for (int r = 0; r < 16; ++r) s = fmaf(w[r], sy[r], s);
        m = fmaxf(s, 0.f);
    }
    ssort[tid] = m;
    __syncthreads();

    sav[tid] = m;
    __syncthreads();
    for (int st = 128; st > 0; st >>= 1) {
        if (tid < st) sav[tid] += sav[tid + st];
        __syncthreads();
    }
    if (tid == 0) {
        g_lasso_part[hb] = sav[0];
        __threadfence();
        int ticket = atomicAdd(&g_lasso_cnt, 1);
        if (ticket == HB_N - 1) {
            if (lasso_out) {
                volatile float* vp = g_lasso_part;
                float s = 0.f;
                for (int i = 0; i < HB_N; ++i) s += vp[i];
                *lasso_out = s * (1.f / (float)(BATCH*CIN));
            }
            g_lasso_cnt = 0;
        }
    }
    __syncthreads();

    for (int k = 2; k <= 256; k <<= 1) {
        for (int j = k >> 1; j > 0; j >>= 1) {
            int ixj = tid ^ j;
            if (ixj > tid) {
                float va = ssort[tid], vb = ssort[ixj];
                bool up = ((tid & k) == 0);
                if ((va > vb) == up) { ssort[tid] = vb; ssort[ixj] = va; }
            }
            __syncthreads();
        }
    }

    int inact = 192;
    if (inact_p) {
        int iv = *inact_p;
        if (iv < 0 || iv > 256) {
            float f = __int_as_float(iv);
            iv = (f >= 0.f && f <= 256.f) ? (int)(f + 0.5f) : 192;
        }
        inact = iv;
    }
    float thresh = (inact > 0) ? ssort[min(inact,256) - 1] : -1e30f;

    bool keep = (m > thresh);
    unsigned ball = __ballot_sync(0xffffffffu, keep);
    int wid = tid >> 5, lane = tid & 31;
    if (lane == 0) wcnt[wid] = __popc(ball);
    __syncthreads();
    if (tid == 0) {
        int o = 0;
        #pragma unroll
        for (int w = 0; w < 8; ++w) { woff[w] = o; o += wcnt[w]; }
        woff[8] = o;
        g_act_cnt[hb] = o;
    }
    __syncthreads();
    int total = woff[8];
    int padded = (total + 15) & ~15;
    if (tid >= total && tid < padded) {
        g_act_idx[hb*256 + tid] = 0;
        g_act_val[hb*256 + tid] = 0.f;
    }
    if (keep) {
        int slot = woff[wid] + __popc(ball & ((1u << lane) - 1));
        g_act_idx[hb*256 + slot] = tid;
        g_act_val[hb*256 + slot] = m;
    }
}

// =====================================================================
// conv staging helpers
// =====================================================================
struct ConstView { int* sch; float* sca; float* scb; float* scm; };

__device__ __forceinline__ void stage_consts(
    ConstView cv, int slot, int ckbase, int cnt, int hb, int tid,
    const float* gmm, const float* bet, const float* mea, const float* var)
{
    if (tid < 16) {
        int pos = ckbase + tid;
        int ch = 0; float mv = 0.f;
        if (pos < cnt) { ch = g_act_idx[hb*256 + pos]; mv = g_act_val[hb*256 + pos]; }
        float a  = gmm[ch] * rsqrtf(var[ch] + BN_EPS);
        cv.sch[slot*16 + tid] = ch;
        cv.sca[slot*16 + tid] = a;
        cv.scb[slot*16 + tid] = bet[ch] - mea[ch] * a;
        cv.scm[slot*16 + tid] = mv;
    }
}

// stage one plane row directly (prologue)
__device__ __forceinline__ void stage_row(
    ConstView cv, int cs, const float* __restrict__ xb, bool xin, size_t xoff,
    char* rowp)
{
    if (!xin) {
        #pragma unroll
        for (int j = 0; j < 8; ++j)
            *(uint32_t*)(rowp + j*4) = 0u;
        return;
    }
    #pragma unroll
    for (int g = 0; g < 2; ++g) {
        float xv[8];
        #pragma unroll
        for (int j = 0; j < 8; ++j)
            xv[j] = xb[(size_t)cv.sch[cs + g*8 + j]*NPIX + xoff];
        #pragma unroll
        for (int j = 0; j < 8; j += 2) {
            int ic = cs + g*8 + j;
            float v0 = fmaxf(fmaf(xv[j],   cv.sca[ic],   cv.scb[ic]),   0.f) * cv.scm[ic];
            float v1 = fmaxf(fmaf(xv[j+1], cv.sca[ic+1], cv.scb[ic+1]), 0.f) * cv.scm[ic+1];
            *(uint32_t*)(rowp + (g*8 + j)*2) = pack_f16(v0, v1);
        }
    }
}

// transform + store one row from prefetched regs
__device__ __forceinline__ void xform_store(
    ConstView cv, int cs, const float* pf, bool xin, char* rowp)
{
    if (!xin) {
        #pragma unroll
        for (int j = 0; j < 8; ++j)
            *(uint32_t*)(rowp + j*4) = 0u;
        return;
    }
    #pragma unroll
    for (int j = 0; j < 16; j += 2) {
        int ic = cs + j;
        float v0 = fmaxf(fmaf(pf[j],   cv.sca[ic],   cv.scb[ic]),   0.f) * cv.scm[ic];
        float v1 = fmaxf(fmaf(pf[j+1], cv.sca[ic+1], cv.scb[ic+1]), 0.f) * cv.scm[ic+1];
        *(uint32_t*)(rowp + j*2) = pack_f16(v0, v1);
    }
}

// weights -> 128B-pitch XOR-swizzled tiles
__device__ __forceinline__ void issue_weights(
    ConstView cv, int slot, uint32_t wdst,
    const uint16_t* whBase, const uint16_t* wlBase, int tid)
{
    #pragma unroll
    for (int i = 0; i < 9; ++i) {
        int idx = tid + i*256;
        int arr = idx >= 1152;
        int r2  = idx - arr*1152;
        int row = r2 >> 3;
        int seg = r2 & 7;
        int ic  = row & 15, t = row >> 4;
        const uint16_t* src = (arr ? wlBase : whBase)
                            + (((t*CIN + cv.sch[slot*16 + ic]) << 6) + seg*8);
        cp16(wdst + (uint32_t)(arr*WTILE_B + row*128 + ((seg<<4) ^ ((row&7)<<4))), src);
    }
    asm volatile("cp.async.commit_group;" ::: "memory");
}

// one conv tap: B first (16 regs), then per-mi ldsm4 + 8 mma
#define TAP_BODY(t)                                                          \
    {                                                                        \
        int ky = (t) / 3, kx = (t) - ky*3;                                   \
        int sb = ((ky - 1)*PGRID + (kx - 1)) * PITCH_PB;                     \
        uint32_t bh[4][2], bl[4][2];                                         \
        uint32_t wb = bB + (uint32_t)((t)*2048);                             \
        ldsm4t(wb + swB0,            &bh[0][0]);                             \
        ldsm4t(wb + swB1,            &bh[2][0]);                             \
        ldsm4t(wb + WTILE_B + swB0,  &bl[0][0]);                             \
        ldsm4t(wb + WTILE_B + swB1,  &bl[2][0]);                             \
        _Pragma("unroll")                                                    \
        for (int mi = 0; mi < 4; ++mi) {                                     \
            uint32_t ah[4];                                                  \
            ldsm4((uint32_t)(aB + sb + mi*768), ah);                         \
            _Pragma("unroll")                                                \
            for (int ni = 0; ni < 4; ++ni) {                                 \
                mma16816(d[mi][ni], ah, bh[ni]);                             \
                mma16816(d[mi][ni], ah, bl[ni]);                             \
            }                                                                \
        }                                                                    \
    }

// =====================================================================
// Kernel 3: sparse grouped conv; M=256 tile, fp16 2-pass,
//  single-barrier pipeline, double-buffered plane + weights.
// =====================================================================
__global__ __launch_bounds__(256, 2)
void conv_mma_kernel(const float* __restrict__ x,
                     const float* __restrict__ gmm,
                     const float* __restrict__ bet,
                     const float* __restrict__ mea,
                     const float* __restrict__ var,
                     float* __restrict__ out)
{
    extern __shared__ __align__(16) char dsm[];
    ConstView cv;
    cv.sch = (int*)(dsm + OFF_C);
    cv.sca = (float*)(dsm + OFF_C + 128);
    cv.scb = (float*)(dsm + OFF_C + 256);
    cv.scm = (float*)(dsm + OFF_C + 384);

    int tid  = threadIdx.x;
    int wid  = tid >> 5, lane = tid & 31;
    int wm   = wid >> 1, wn = wid & 1;
    int grp  = lane >> 2, qd = lane & 3;

    int hb = blockIdx.y;
    int h  = hb >> 4, b = hb & 15;
    int q0 = blockIdx.x * MTILE;

    // row1 = tid; row2 = tid + 256 (only tid < PLROWS-256)
    int pg1 = q0 - 59 + tid;
    bool in1 = (pg1 >= 0) && (pg1 < PTOT);
    int rp1 = pg1 / PGRID, cp1 = pg1 - rp1*PGRID;
    int rr1 = rp1 - 1, cc1 = cp1 - 1;
    bool xin1 = in1 && ((unsigned)rr1 < (unsigned)HH) && ((unsigned)cc1 < (unsigned)WW);
    size_t xoff1 = (size_t)rr1*WW + cc1;

    bool has2 = (tid < PLROWS - 256);   // 118 threads
    int pg2 = q0 - 59 + tid + 256;
    bool in2 = has2 && (pg2 >= 0) && (pg2 < PTOT);
    int rp2_ = pg2 / PGRID, cp2_ = pg2 - rp2_*PGRID;
    int rr2 = rp2_ - 1, cc2 = cp2_ - 1;
    bool xin2 = in2 && ((unsigned)rr2 < (unsigned)HH) && ((unsigned)cc2 < (unsigned)WW);
    size_t xoff2 = (size_t)rr2*WW + cc2;

    const float* xb = x + (size_t)b*CIN*NPIX;

    int cnt = g_act_cnt[hb];
    int nchunks = (cnt + 15) >> 4;

    float d[4][4][4];
    #pragma unroll
    for (int mi = 0; mi < 4; ++mi)
        #pragma unroll
        for (int ni = 0; ni < 4; ++ni)
            #pragma unroll
            for (int k = 0; k < 4; ++k) d[mi][ni][k] = 0.f;

    uint32_t smb = smem_u32(dsm);
    uint32_t aOff = (uint32_t)((59 + wm*64 + (lane & 15))*PITCH_PB + ((lane >> 4) << 4));
    uint32_t bc0  = (uint32_t)(wn*64 + ((lane >> 4) << 4));
    uint32_t swB0 = (uint32_t)((lane & 15)*128) + (bc0 ^ (uint32_t)((lane & 7) << 4));
    uint32_t swB1 = swB0 ^ 32u;

    const uint16_t* whBase = g_wh + ((size_t)h*9*CIN << 6);
    const uint16_t* wlBase = g_wl + ((size_t)h*9*CIN << 6);

    // ---- prologue
    stage_consts(cv, 0, 0, cnt, hb, tid, gmm, bet, mea, var);
    __syncthreads();
    issue_weights(cv, 0, smb + OFF_W0H, whBase, wlBase, tid);
    stage_row(cv, 0, xb, xin1, xoff1, dsm + OFF_P0 + tid*PITCH_PB);
    if (has2)
        stage_row(cv, 0, xb, xin2, xoff2, dsm + OFF_P0 + (tid + 256)*PITCH_PB);
    if (nchunks > 1)
        stage_consts(cv, 1, 16, cnt, hb, tid, gmm, bet, mea, var);

    #pragma unroll 1
    for (int ck = 0; ck < nchunks; ++ck) {
        int buf = ck & 1;

        asm volatile("cp.async.wait_group 0;" ::: "memory");
        __syncthreads();   // B1

        if (ck + 1 < nchunks)
            issue_weights(cv, buf^1, smb + (buf ? OFF_W0H : OFF_W1H), whBase, wlBase, tid);
        if (ck + 2 < nchunks)
            stage_consts(cv, buf, (ck+2)*16, cnt, hb, tid, gmm, bet, mea, var);

        bool stg = (ck + 1 < nchunks);
        int csN = (buf^1)*16;
        float pf[16];
        char* pNext = dsm + (buf ? OFF_P0 : OFF_P1);

        uint32_t aB = smb + (buf ? OFF_P1 : OFF_P0) + aOff;
        uint32_t bB = smb + (buf ? OFF_W1H : OFF_W0H);

        // row1 prefetch
        if (stg && xin1) {
            #pragma unroll
            for (int j = 0; j < 8; ++j)
                pf[j] = xb[(size_t)cv.sch[csN + j]*NPIX + xoff1];
        }
        TAP_BODY(0)
        if (stg && xin1) {
            #pragma unroll
            for (int j = 0; j < 8; ++j)
                pf[8+j] = xb[(size_t)cv.sch[csN + 8 + j]*NPIX + xoff1];
        }
        TAP_BODY(1) TAP_BODY(2)
        if (stg)
            xform_store(cv, csN, pf, xin1, pNext + tid*PITCH_PB);
        TAP_BODY(3)
        // row2 prefetch (reuse pf)
        if (stg && xin2) {
            #pragma unroll
            for (int j = 0; j < 8; ++j)
                pf[j] = xb[(size_t)cv.sch[csN + j]*NPIX + xoff2];
        }
        TAP_BODY(4)
        if (stg && xin2) {
            #pragma unroll
            for (int j = 0; j < 8; ++j)
                pf[8+j] = xb[(size_t)cv.sch[csN + 8 + j]*NPIX + xoff2];
        }
        TAP_BODY(5) TAP_BODY(6)
        if (stg && has2)
            xform_store(cv, csN, pf, xin2, pNext + (tid + 256)*PITCH_PB);
        TAP_BODY(7) TAP_BODY(8)
    }

    // ---- epilogue
    #pragma unroll
    for (int mi = 0; mi < 4; ++mi) {
        #pragma unroll
        for (int dr = 0; dr < 2; ++dr) {
            int row = wm*64 + mi*16 + dr*8 + grp;
            int q   = q0 + row;
            int rpo = q / PGRID, cpo = q - rpo*PGRID;
            bool v = (rpo >= 1) && (rpo <= HH) && (cpo >= 1) && (cpo <= WW);
            if (v) {
                size_t ob = ((size_t)b*(HEADS*CPER) + h)*NPIX
                          + (size_t)(rpo-1)*WW + (cpo-1);
                #pragma unroll
                for (int ni = 0; ni < 4; ++ni) {
                    int oc = wn*32 + ni*8 + qd*2;
                    out[ob + (size_t)(oc*HEADS)*NPIX]     = d[mi][ni][dr*2 + 0];
                    out[ob + (size_t)((oc+1)*HEADS)*NPIX] = d[mi][ni][dr*2 + 1];
                }
            }
        }
    }
}

// =====================================================================
extern "C" void kernel_launch(void* const* d_in, const int* in_sizes, int n_in,
                              void* d_out, int out_size)
{
    const float* x    = (const float*)d_in[0];
    const float* gmm  = (const float*)d_in[1];
    const float* bet  = (const float*)d_in[2];
    const float* mea  = (const float*)d_in[3];
    const float* var  = (const float*)d_in[4];
    const float* fc1  = (const float*)d_in[5];
    const float* fc2  = (const float*)d_in[6];
    const float* fcb  = (const float*)d_in[7];
    const float* cw   = (const float*)d_in[8];
    const int*   inact = (n_in > 9) ? (const int*)d_in[9] : nullptr;
    float* out = (float*)d_out;
    float* lasso_out = (out_size > NOUT) ? (out + NOUT) : nullptr;

    bn_pool_kernel<<<BATCH*CIN, 256>>>(x, gmm, bet, mea, var);
    wsplit_kernel<<<(HEADS*9*CIN*CPER + 255)/256, 256>>>(cw);
    se_kernel<<<HB_N, 256>>>(fc1, fc2, fcb, inact, lasso_out);

    cudaFuncSetAttribute(conv_mma_kernel, cudaFuncAttributeMaxDynamicSharedMemorySize,
                         SMEM_BYTES);
    dim3 grid(NTILES, HB_N);
    conv_mma_kernel<<<grid, 256, SMEM_BYTES>>>(x, gmm, bet, mea, var, out);
}

// round 17
// speedup vs baseline: 1.8543x; 1.3014x over previous
#include <cuda_runtime.h>
#include <cuda_bf16.h>
#include <cuda_fp16.h>
#include <math.h>
#include <stdint.h>

#define BATCH   16
#define CIN     256
#define HH      56
#define WW      56
#define HEADS   4
#define CPER    64
#define HB_N    64
#define NPIX    3136
#define NOUT    (BATCH*HEADS*CPER*NPIX)
#define BN_EPS  1e-5f

#define PGRID   58
#define PTOT    (PGRID*PGRID)
#define MTILE   256
#define NTILES  13
#define PLROWS  374              // 256 + 2*59 halo
#define PITCH_PB 48              // bytes per plane row: [16 ic fp16 | pad]

// dynamic smem byte offsets
#define WTILE_B  18432           // 144 rows * 128 B (XOR-swizzled)
#define OFF_W0   0
#define OFF_W1   18432
#define OFF_P0   36864           // 374*48 = 17952
#define OFF_P1   54816
#define OFF_C    72768           // sch[2][16], sca[2][16], scb[2][16], scm[2][16]
#define SMEM_BYTES 73280

__device__ float g_xavg[BATCH*CIN];
__device__ int   g_act_idx[HB_N*256];
__device__ float g_act_val[HB_N*256];
__device__ int   g_act_cnt[HB_N];
__device__ float g_lasso_part[HB_N];
__device__ int   g_lasso_cnt = 0;
__device__ __align__(16) uint16_t g_wh[HEADS*9*CIN*CPER];  // fp16, [h][t][c][oc]

// ------------------------- helpers -------------------------
__device__ __forceinline__ uint32_t smem_u32(const void* p) {
    uint32_t a;
    asm("{ .reg .u64 t; cvta.to.shared.u64 t, %1; cvt.u32.u64 %0, t; }" : "=r"(a) : "l"(p));
    return a;
}
__device__ __forceinline__ void ldsm4(uint32_t addr, uint32_t* r) {
    asm("ldmatrix.sync.aligned.m8n8.x4.shared.b16 {%0,%1,%2,%3}, [%4];"
        : "=r"(r[0]), "=r"(r[1]), "=r"(r[2]), "=r"(r[3]) : "r"(addr));
}
__device__ __forceinline__ void ldsm4t(uint32_t addr, uint32_t* r) {
    asm("ldmatrix.sync.aligned.m8n8.x4.trans.shared.b16 {%0,%1,%2,%3}, [%4];"
        : "=r"(r[0]), "=r"(r[1]), "=r"(r[2]), "=r"(r[3]) : "r"(addr));
}
__device__ __forceinline__ void mma16816(float* d, const uint32_t* a, const uint32_t* b) {
    asm("mma.sync.aligned.m16n8k16.row.col.f32.f16.f16.f32 "
        "{%0,%1,%2,%3}, {%4,%5,%6,%7}, {%8,%9}, {%0,%1,%2,%3};"
        : "+f"(d[0]), "+f"(d[1]), "+f"(d[2]), "+f"(d[3])
        : "r"(a[0]), "r"(a[1]), "r"(a[2]), "r"(a[3]), "r"(b[0]), "r"(b[1]));
}
__device__ __forceinline__ void cp16(uint32_t dst, const void* src) {
    asm volatile("cp.async.cg.shared.global [%0], [%1], 16;"
                 :: "r"(dst), "l"(src) : "memory");
}
__device__ __forceinline__ uint32_t pack_f16(float e, float o) {
    uint32_t r;
    asm("cvt.rn.f16x2.f32 %0, %1, %2;" : "=r"(r) : "f"(o), "f"(e));
    return r;
}

// =====================================================================
// Kernel 0: weight fp16 -> [h][t][c][oc]
// =====================================================================
__global__ void wsplit_kernel(const float* __restrict__ cw)
{
    int idx = blockIdx.x*256 + threadIdx.x;
    if (idx >= HEADS*9*CIN*CPER) return;
    int oc  = idx & 63;
    int c   = (idx >> 6) & 255;
    int ht  = idx >> 14;
    int t   = ht % 9;
    int h   = ht / 9;
    float w = cw[(((size_t)(h*CPER + oc))*CIN + c)*9 + t];
    g_wh[idx] = __half_as_ushort(__float2half(w));
}

// =====================================================================
// Kernel 1: BN+ReLU fused global average pool
// =====================================================================
__global__ void bn_pool_kernel(const float* __restrict__ x,
                               const float* __restrict__ gmm,
                               const float* __restrict__ bet,
                               const float* __restrict__ mea,
                               const float* __restrict__ var)
{
    int bc = blockIdx.x;
    int c  = bc & (CIN-1);
    float a  = gmm[c] * rsqrtf(var[c] + BN_EPS);
    float sh = bet[c] - mea[c] * a;
    const float4* xp = (const float4*)(x + (size_t)bc * NPIX);
    float s = 0.f;
    for (int i = threadIdx.x; i < NPIX/4; i += 256) {
        float4 v = xp[i];
        s += fmaxf(fmaf(v.x, a, sh), 0.f) + fmaxf(fmaf(v.y, a, sh), 0.f)
           + fmaxf(fmaf(v.z, a, sh), 0.f) + fmaxf(fmaf(v.w, a, sh), 0.f);
    }
    #pragma unroll
    for (int o = 16; o; o >>= 1) s += __shfl_xor_sync(0xffffffffu, s, o);
    __shared__ float r8[8];
    if ((threadIdx.x & 31) == 0) r8[threadIdx.x >> 5] = s;
    __syncthreads();
    if (threadIdx.x < 8) {
        float v = r8[threadIdx.x];
        #pragma unroll
        for (int o = 4; o; o >>= 1) v += __shfl_xor_sync(0xffu, v, o);
        if (threadIdx.x == 0) g_xavg[bc] = v * (1.f / (float)NPIX);
    }
}

// =====================================================================
// Kernel 2: SE gate + exact top-k threshold + compaction + lasso
// =====================================================================
__global__ void se_kernel(const float* __restrict__ fc1,
                          const float* __restrict__ fc2,
                          const float* __restrict__ fcb,
                          const int*   inact_p,
                          float*       lasso_out)
{
    __shared__ float sav[256];
    __shared__ float sy[16];
    __shared__ float ssort[256];
    __shared__ int   wcnt[8];
    __shared__ int   woff[9];

    int hb = blockIdx.x;
    int h  = hb >> 4, b = hb & 15;
    int tid = threadIdx.x;

    sav[tid] = g_xavg[b*CIN + tid];
    __syncthreads();

    if (tid < 16) {
        const float* w = fc1 + (h*16 + tid)*256;
        float s = 0.f;
        #pragma unroll 8
        for (int c = 0; c < 256; ++c) s = fmaf(w[c], sav[c], s);
        sy[tid] = fmaxf(s, 0.f);
    }
    __syncthreads();

    float m;
    {
        const float* w = fc2 + ((size_t)(h*256 + tid)) * 16;
        float s = fcb[h*256 + tid];
        #pragma unroll
        for (int r = 0; r < 16; ++r) s = fmaf(w[r], sy[r], s);
        m = fmaxf(s, 0.f);
    }
    ssort[tid] = m;
    __syncthreads();

    sav[tid] = m;
    __syncthreads();
    for (int st = 128; st > 0; st >>= 1) {
        if (tid < st) sav[tid] += sav[tid + st];
        __syncthreads();
    }
    if (tid == 0) {
        g_lasso_part[hb] = sav[0];
        __threadfence();
        int ticket = atomicAdd(&g_lasso_cnt, 1);
        if (ticket == HB_N - 1) {
            if (lasso_out) {
                volatile float* vp = g_lasso_part;
                float s = 0.f;
                for (int i = 0; i < HB_N; ++i) s += vp[i];
                *lasso_out = s * (1.f / (float)(BATCH*CIN));
            }
            g_lasso_cnt = 0;
        }
    }
    __syncthreads();

    for (int k = 2; k <= 256; k <<= 1) {
        for (int j = k >> 1; j > 0; j >>= 1) {
            int ixj = tid ^ j;
            if (ixj > tid) {
                float va = ssort[tid], vb = ssort[ixj];
                bool up = ((tid & k) == 0);
                if ((va > vb) == up) { ssort[tid] = vb; ssort[ixj] = va; }
            }
            __syncthreads();
        }
    }

    int inact = 192;
    if (inact_p) {
        int iv = *inact_p;
        if (iv < 0 || iv > 256) {
            float f = __int_as_float(iv);
            iv = (f >= 0.f && f <= 256.f) ? (int)(f + 0.5f) : 192;
        }
        inact = iv;
    }
    float thresh = (inact > 0) ? ssort[min(inact,256) - 1] : -1e30f;

    bool keep = (m > thresh);
    unsigned ball = __ballot_sync(0xffffffffu, keep);
    int wid = tid >> 5, lane = tid & 31;
    if (lane == 0) wcnt[wid] = __popc(ball);
    __syncthreads();
    if (tid == 0) {
        int o = 0;
        #pragma unroll
        for (int w = 0; w < 8; ++w) { woff[w] = o; o += wcnt[w]; }
        woff[8] = o;
        g_act_cnt[hb] = o;
    }
    __syncthreads();
    int total = woff[8];
    int padded = (total + 15) & ~15;
    if (tid >= total && tid < padded) {
        g_act_idx[hb*256 + tid] = 0;
        g_act_val[hb*256 + tid] = 0.f;
    }
    if (keep) {
        int slot = woff[wid] + __popc(ball & ((1u << lane) - 1));
        g_act_idx[hb*256 + slot] = tid;
        g_act_val[hb*256 + slot] = m;
    }
}

// =====================================================================
// conv staging helpers
// =====================================================================
struct ConstView { int* sch; float* sca; float* scb; float* scm; };

__device__ __forceinline__ void stage_consts(
    ConstView cv, int slot, int ckbase, int cnt, int hb, int tid,
    const float* gmm, const float* bet, const float* mea, const float* var)
{
    if (tid < 16) {
        int pos = ckbase + tid;
        int ch = 0; float mv = 0.f;
        if (pos < cnt) { ch = g_act_idx[hb*256 + pos]; mv = g_act_val[hb*256 + pos]; }
        float a  = gmm[ch] * rsqrtf(var[ch] + BN_EPS);
        cv.sch[slot*16 + tid] = ch;
        cv.sca[slot*16 + tid] = a;
        cv.scb[slot*16 + tid] = bet[ch] - mea[ch] * a;
        cv.scm[slot*16 + tid] = mv;
    }
}

// stage one plane row directly (prologue)
__device__ __forceinline__ void stage_row(
    ConstView cv, int cs, const float* __restrict__ xb, bool xin, size_t xoff,
    char* rowp)
{
    if (!xin) {
        #pragma unroll
        for (int j = 0; j < 8; ++j)
            *(uint32_t*)(rowp + j*4) = 0u;
        return;
    }
    #pragma unroll
    for (int g = 0; g < 2; ++g) {
        float xv[8];
        #pragma unroll
        for (int j = 0; j < 8; ++j)
            xv[j] = xb[(size_t)cv.sch[cs + g*8 + j]*NPIX + xoff];
        #pragma unroll
        for (int j = 0; j < 8; j += 2) {
            int ic = cs + g*8 + j;
            float v0 = fmaxf(fmaf(xv[j],   cv.sca[ic],   cv.scb[ic]),   0.f) * cv.scm[ic];
            float v1 = fmaxf(fmaf(xv[j+1], cv.sca[ic+1], cv.scb[ic+1]), 0.f) * cv.scm[ic+1];
            *(uint32_t*)(rowp + (g*8 + j)*2) = pack_f16(v0, v1);
        }
    }
}

// transform + store one row from prefetched regs
__device__ __forceinline__ void xform_store(
    ConstView cv, int cs, const float* pf, bool xin, char* rowp)
{
    if (!xin) {
        #pragma unroll
        for (int j = 0; j < 8; ++j)
            *(uint32_t*)(rowp + j*4) = 0u;
        return;
    }
    #pragma unroll
    for (int j = 0; j < 16; j += 2) {
        int ic = cs + j;
        float v0 = fmaxf(fmaf(pf[j],   cv.sca[ic],   cv.scb[ic]),   0.f) * cv.scm[ic];
        float v1 = fmaxf(fmaf(pf[j+1], cv.sca[ic+1], cv.scb[ic+1]), 0.f) * cv.scm[ic+1];
        *(uint32_t*)(rowp + j*2) = pack_f16(v0, v1);
    }
}

// weights -> 128B-pitch XOR-swizzled tile (1152 fp16x8 segments)
__device__ __forceinline__ void issue_weights(
    ConstView cv, int slot, uint32_t wdst,
    const uint16_t* whBase, int tid)
{
    #pragma unroll
    for (int i = 0; i < 5; ++i) {
        int idx = tid + i*256;                 // 0..1279, valid < 1152
        if (idx < 1152) {
            int row = idx >> 3;                // t*16+ic (0..143)
            int seg = idx & 7;
            int ic  = row & 15, t = row >> 4;
            const uint16_t* src = whBase + (((t*CIN + cv.sch[slot*16 + ic]) << 6) + seg*8);
            cp16(wdst + (uint32_t)(row*128 + ((seg<<4) ^ ((row&7)<<4))), src);
        }
    }
    asm volatile("cp.async.commit_group;" ::: "memory");
}

// one conv tap: 2 ldsm4t (B), then per-mi ldsm4 + 4 mma
#define TAP_BODY(t)                                                          \
    {                                                                        \
        int ky = (t) / 3, kx = (t) - ky*3;                                   \
        int sb = ((ky - 1)*PGRID + (kx - 1)) * PITCH_PB;                     \
        uint32_t bh[4][2];                                                   \
        uint32_t wb = bB + (uint32_t)((t)*2048);                             \
        ldsm4t(wb + swB0, &bh[0][0]);                                        \
        ldsm4t(wb + swB1, &bh[2][0]);                                        \
        _Pragma("unroll")                                                    \
        for (int mi = 0; mi < 4; ++mi) {                                     \
            uint32_t ah[4];                                                  \
            ldsm4((uint32_t)(aB + sb + mi*768), ah);                         \
            _Pragma("unroll")                                                \
            for (int ni = 0; ni < 4; ++ni)                                   \
                mma16816(d[mi][ni], ah, bh[ni]);                             \
        }                                                                    \
    }

// =====================================================================
// Kernel 3: sparse grouped conv; M=256 tile, single-pass fp16,
//  single-barrier pipeline, double-buffered plane + weights.
// =====================================================================
__global__ __launch_bounds__(256, 2)
void conv_mma_kernel(const float* __restrict__ x,
                     const float* __restrict__ gmm,
                     const float* __restrict__ bet,
                     const float* __restrict__ mea,
                     const float* __restrict__ var,
                     float* __restrict__ out)
{
    extern __shared__ __align__(16) char dsm[];
    ConstView cv;
    cv.sch = (int*)(dsm + OFF_C);
    cv.sca = (float*)(dsm + OFF_C + 128);
    cv.scb = (float*)(dsm + OFF_C + 256);
    cv.scm = (float*)(dsm + OFF_C + 384);

    int tid  = threadIdx.x;
    int wid  = tid >> 5, lane = tid & 31;
    int wm   = wid >> 1, wn = wid & 1;
    int grp  = lane >> 2, qd = lane & 3;

    int hb = blockIdx.y;
    int h  = hb >> 4, b = hb & 15;
    int q0 = blockIdx.x * MTILE;

    int pg1 = q0 - 59 + tid;
    bool in1 = (pg1 >= 0) && (pg1 < PTOT);
    int rp1 = pg1 / PGRID, cp1 = pg1 - rp1*PGRID;
    int rr1 = rp1 - 1, cc1 = cp1 - 1;
    bool xin1 = in1 && ((unsigned)rr1 < (unsigned)HH) && ((unsigned)cc1 < (unsigned)WW);
    size_t xoff1 = (size_t)rr1*WW + cc1;

    bool has2 = (tid < PLROWS - 256);   // 118 threads
    int pg2 = q0 - 59 + tid + 256;
    bool in2 = has2 && (pg2 >= 0) && (pg2 < PTOT);
    int rp2_ = pg2 / PGRID, cp2_ = pg2 - rp2_*PGRID;
    int rr2 = rp2_ - 1, cc2 = cp2_ - 1;
    bool xin2 = in2 && ((unsigned)rr2 < (unsigned)HH) && ((unsigned)cc2 < (unsigned)WW);
    size_t xoff2 = (size_t)rr2*WW + cc2;

    const float* xb = x + (size_t)b*CIN*NPIX;

    int cnt = g_act_cnt[hb];
    int nchunks = (cnt + 15) >> 4;

    float d[4][4][4];
    #pragma unroll
    for (int mi = 0; mi < 4; ++mi)
        #pragma unroll
        for (int ni = 0; ni < 4; ++ni)
            #pragma unroll
            for (int k = 0; k < 4; ++k) d[mi][ni][k] = 0.f;

    uint32_t smb = smem_u32(dsm);
    uint32_t aOff = (uint32_t)((59 + wm*64 + (lane & 15))*PITCH_PB + ((lane >> 4) << 4));
    uint32_t bc0  = (uint32_t)(wn*64 + ((lane >> 4) << 4));
    uint32_t swB0 = (uint32_t)((lane & 15)*128) + (bc0 ^ (uint32_t)((lane & 7) << 4));
    uint32_t swB1 = swB0 ^ 32u;

    const uint16_t* whBase = g_wh + ((size_t)h*9*CIN << 6);

    // ---- prologue
    stage_consts(cv, 0, 0, cnt, hb, tid, gmm, bet, mea, var);
    __syncthreads();
    issue_weights(cv, 0, smb + OFF_W0, whBase, tid);
    stage_row(cv, 0, xb, xin1, xoff1, dsm + OFF_P0 + tid*PITCH_PB);
    if (has2)
        stage_row(cv, 0, xb, xin2, xoff2, dsm + OFF_P0 + (tid + 256)*PITCH_PB);
    if (nchunks > 1)
        stage_consts(cv, 1, 16, cnt, hb, tid, gmm, bet, mea, var);

    #pragma unroll 1
    for (int ck = 0; ck < nchunks; ++ck) {
        int buf = ck & 1;

        asm volatile("cp.async.wait_group 0;" ::: "memory");
        __syncthreads();   // B1

        if (ck + 1 < nchunks)
            issue_weights(cv, buf^1, smb + (buf ? OFF_W0 : OFF_W1), whBase, tid);
        if (ck + 2 < nchunks)
            stage_consts(cv, buf, (ck+2)*16, cnt, hb, tid, gmm, bet, mea, var);

        bool stg = (ck + 1 < nchunks);
        int csN = (buf^1)*16;
        float pf[16];
        char* pNext = dsm + (buf ? OFF_P0 : OFF_P1);

        uint32_t aB = smb + (buf ? OFF_P1 : OFF_P0) + aOff;
        uint32_t bB = smb + (buf ? OFF_W1 : OFF_W0);

        if (stg && xin1) {
            #pragma unroll
            for (int j = 0; j < 8; ++j)
                pf[j] = xb[(size_t)cv.sch[csN + j]*NPIX + xoff1];
        }
        TAP_BODY(0)
        if (stg && xin1) {
            #pragma unroll
            for (int j = 0; j < 8; ++j)
                pf[8+j] = xb[(size_t)cv.sch[csN + 8 + j]*NPIX + xoff1];
        }
        TAP_BODY(1) TAP_BODY(2)
        if (stg)
            xform_store(cv, csN, pf, xin1, pNext + tid*PITCH_PB);
        TAP_BODY(3)
        if (stg && xin2) {
            #pragma unroll
            for (int j = 0; j < 8; ++j)
                pf[j] = xb[(size_t)cv.sch[csN + j]*NPIX + xoff2];
        }
        TAP_BODY(4)
        if (stg && xin2) {
            #pragma unroll
            for (int j = 0; j < 8; ++j)
                pf[8+j] = xb[(size_t)cv.sch[csN + 8 + j]*NPIX + xoff2];
        }
        TAP_BODY(5) TAP_BODY(6)
        if (stg && has2)
            xform_store(cv, csN, pf, xin2, pNext + (tid + 256)*PITCH_PB);
        TAP_BODY(7) TAP_BODY(8)
    }

    // ---- epilogue
    #pragma unroll
    for (int mi = 0; mi < 4; ++mi) {
        #pragma unroll
        for (int dr = 0; dr < 2; ++dr) {
            int row = wm*64 + mi*16 + dr*8 + grp;
            int q   = q0 + row;
            int rpo = q / PGRID, cpo = q - rpo*PGRID;
            bool v = (rpo >= 1) && (rpo <= HH) && (cpo >= 1) && (cpo <= WW);
            if (v) {
                size_t ob = ((size_t)b*(HEADS*CPER) + h)*NPIX
                          + (size_t)(rpo-1)*WW + (cpo-1);
                #pragma unroll
                for (int ni = 0; ni < 4; ++ni) {
                    int oc = wn*32 + ni*8 + qd*2;
                    out[ob + (size_t)(oc*HEADS)*NPIX]     = d[mi][ni][dr*2 + 0];
                    out[ob + (size_t)((oc+1)*HEADS)*NPIX] = d[mi][ni][dr*2 + 1];
                }
            }
        }
    }
}

// =====================================================================
extern "C" void kernel_launch(void* const* d_in, const int* in_sizes, int n_in,
                              void* d_out, int out_size)
{
    const float* x    = (const float*)d_in[0];
    const float* gmm  = (const float*)d_in[1];
    const float* bet  = (const float*)d_in[2];
    const float* mea  = (const float*)d_in[3];
    const float* var  = (const float*)d_in[4];
    const float* fc1  = (const float*)d_in[5];
    const float* fc2  = (const float*)d_in[6];
    const float* fcb  = (const float*)d_in[7];
    const float* cw   = (const float*)d_in[8];
    const int*   inact = (n_in > 9) ? (const int*)d_in[9] : nullptr;
    float* out = (float*)d_out;
    float* lasso_out = (out_size > NOUT) ? (out + NOUT) : nullptr;

    bn_pool_kernel<<<BATCH*CIN, 256>>>(x, gmm, bet, mea, var);
    wsplit_kernel<<<(HEADS*9*CIN*CPER + 255)/256, 256>>>(cw);
    se_kernel<<<HB_N, 256>>>(fc1, fc2, fcb, inact, lasso_out);

    cudaFuncSetAttribute(conv_mma_kernel, cudaFuncAttributeMaxDynamicSharedMemorySize,
                         SMEM_BYTES);
    dim3 grid(NTILES, HB_N);
    conv_mma_kernel<<<grid, 256, SMEM_BYTES>>>(x, gmm, bet, mea, var, out);
}